// round 12
// baseline (speedup 1.0000x reference)
#include <cuda_runtime.h>
#include <cuda_bf16.h>
#include <cuda_fp16.h>
#include <stdint.h>
#include <math.h>

typedef __nv_bfloat16 bf16;
typedef unsigned long long u64;
typedef unsigned int u32;

#define T_TOK 4096
#define HDIM  1024
#define IDIM  2048
#define NEXP  8
#define SLOTS (2 * T_TOK)

// ======================= scratch (device globals) =======================
// router path (bf16 4-pass, exact top-k)
__device__ __align__(16) bf16 g_tch[(size_t)T_TOK * HDIM];
__device__ __align__(16) bf16 g_tcl[(size_t)T_TOK * HDIM];
__device__ __align__(16) bf16 g_tpwT_h[(size_t)HDIM * HDIM];
__device__ __align__(16) bf16 g_tpwT_l[(size_t)HDIM * HDIM];
__device__ float g_xr[(size_t)T_TOK * HDIM];

// fp16 single-pass path (gate/up weights INTERLEAVED: even row=gate, odd row=up)
__device__ __align__(16) __half g_x16[(size_t)T_TOK * HDIM];
__device__ __align__(16) __half g_sguT[(size_t)(2 * IDIM) * HDIM];
__device__ __align__(16) __half g_eguT[(size_t)NEXP * (2 * IDIM) * HDIM];
__device__ __align__(16) __half g_sdT16[(size_t)HDIM * IDIM];
__device__ __align__(16) __half g_edT16[(size_t)NEXP * HDIM * IDIM];
__device__ __align__(16) __half g_hs16[(size_t)T_TOK * IDIM];
__device__ __align__(16) __half g_he16[(size_t)SLOTS * IDIM];

__device__ float g_eout[(size_t)SLOTS * HDIM];

// routing
__device__ int   g_tok_e[T_TOK * 2];
__device__ float g_tok_w[T_TOK * 2];
__device__ int   g_tok_slot[T_TOK * 2];
__device__ int   g_counts[NEXP];
__device__ int   g_offsets[NEXP];
__device__ int   g_cursor[NEXP];
__device__ int   g_list_tok[SLOTS];
__device__ float g_list_w[SLOTS];

// ======================= PTX helpers (sm_80-era, compute_103-safe) =======================
__device__ __forceinline__ u32 smem_u32(const void* p) {
    u32 a;
    asm("{ .reg .u64 t; cvta.to.shared.u64 t, %1; cvt.u32.u64 %0, t; }" : "=r"(a) : "l"(p));
    return a;
}
__device__ __forceinline__ void cpa16(u32 dst, const void* src) {
    asm volatile("cp.async.cg.shared.global [%0], [%1], 16;"
                 :: "r"(dst), "l"(src) : "memory");
}
__device__ __forceinline__ void cpa_commit() {
    asm volatile("cp.async.commit_group;" ::: "memory");
}
__device__ __forceinline__ void ldsm4(u32* r, u32 addr) {
    asm volatile("ldmatrix.sync.aligned.m8n8.x4.shared.b16 {%0,%1,%2,%3}, [%4];"
                 : "=r"(r[0]), "=r"(r[1]), "=r"(r[2]), "=r"(r[3]) : "r"(addr));
}
__device__ __forceinline__ void mma_bf16(float* c, const u32* a, u32 b0, u32 b1) {
    asm volatile("mma.sync.aligned.m16n8k16.row.col.f32.bf16.bf16.f32 "
                 "{%0,%1,%2,%3}, {%4,%5,%6,%7}, {%8,%9}, {%0,%1,%2,%3};"
                 : "+f"(c[0]), "+f"(c[1]), "+f"(c[2]), "+f"(c[3])
                 : "r"(a[0]), "r"(a[1]), "r"(a[2]), "r"(a[3]), "r"(b0), "r"(b1));
}
__device__ __forceinline__ void mma_f16(float* c, const u32* a, u32 b0, u32 b1) {
    asm volatile("mma.sync.aligned.m16n8k16.row.col.f32.f16.f16.f32 "
                 "{%0,%1,%2,%3}, {%4,%5,%6,%7}, {%8,%9}, {%0,%1,%2,%3};"
                 : "+f"(c[0]), "+f"(c[1]), "+f"(c[2]), "+f"(c[3])
                 : "r"(a[0]), "r"(a[1]), "r"(a[2]), "r"(a[3]), "r"(b0), "r"(b1));
}

// ======================= small kernels =======================
__global__ void k_init() {
    int i = threadIdx.x;
    if (i < NEXP) { g_counts[i] = 0; g_cursor[i] = 0; }
}

// fp32 -> bf16 hi/lo (router activations)
__global__ void k_split(const float* __restrict__ S, bf16* __restrict__ H,
                        bf16* __restrict__ L, int n4) {
    int i = blockIdx.x * blockDim.x + threadIdx.x;
    if (i >= n4) return;
    float4 v = ((const float4*)S)[i];
    union { bf16 b[4]; ushort4 u; } uh, ul;
    float vv[4] = { v.x, v.y, v.z, v.w };
#pragma unroll
    for (int j = 0; j < 4; j++) {
        bf16 h = __float2bfloat16(vv[j]);
        uh.b[j] = h;
        ul.b[j] = __float2bfloat16(vv[j] - __bfloat162float(h));
    }
    ((ushort4*)H)[i] = uh.u;
    ((ushort4*)L)[i] = ul.u;
}

// fp32 -> fp16 (single limb)
__global__ void k_cvt16(const float* __restrict__ S, __half* __restrict__ H, int n4) {
    int i = blockIdx.x * blockDim.x + threadIdx.x;
    if (i >= n4) return;
    float4 v = ((const float4*)S)[i];
    union { __half b[4]; uint2 u; } uh;
    uh.b[0] = __float2half_rn(v.x); uh.b[1] = __float2half_rn(v.y);
    uh.b[2] = __float2half_rn(v.z); uh.b[3] = __float2half_rn(v.w);
    ((uint2*)H)[i] = uh.u;
}

// transpose + bf16 split (router weights)
__global__ void k_tsplit(const float* __restrict__ W, bf16* __restrict__ Th,
                         bf16* __restrict__ Tl, int K, int N) {
    __shared__ float t[32][33];
    int k0 = blockIdx.y * 32, n0 = blockIdx.x * 32;
    int tx = threadIdx.x, ty = threadIdx.y;
#pragma unroll
    for (int q = 0; q < 4; q++)
        t[ty + 8 * q][tx] = W[(size_t)(k0 + ty + 8 * q) * N + n0 + tx];
    __syncthreads();
#pragma unroll
    for (int q = 0; q < 4; q++) {
        int n = ty + 8 * q;
        float v = t[tx][n];
        bf16 h = __float2bfloat16(v);
        bf16 l = __float2bfloat16(v - __bfloat162float(h));
        size_t o = (size_t)(n0 + n) * K + k0 + tx;
        Th[o] = h; Tl[o] = l;
    }
}

// transpose + single fp16: W [K,N] (+z*srcZ) -> T rows (n*rowmul + phase) (+z*dstZ)
__global__ void k_t16(const float* __restrict__ W, __half* __restrict__ T,
                      int K, int N, size_t srcZ, size_t dstZ, int rowmul, int phase) {
    W += (size_t)blockIdx.z * srcZ; T += (size_t)blockIdx.z * dstZ;
    __shared__ float t[32][33];
    int k0 = blockIdx.y * 32, n0 = blockIdx.x * 32;
    int tx = threadIdx.x, ty = threadIdx.y;
#pragma unroll
    for (int q = 0; q < 4; q++)
        t[ty + 8 * q][tx] = W[(size_t)(k0 + ty + 8 * q) * N + n0 + tx];
    __syncthreads();
#pragma unroll
    for (int q = 0; q < 4; q++) {
        int n = ty + 8 * q;
        T[(size_t)((n0 + n) * rowmul + phase) * K + k0 + tx] = __float2half_rn(t[tx][n]);
    }
}

__global__ void k_gate(const float* __restrict__ gw) {
    int t = (blockIdx.x * blockDim.x + threadIdx.x) >> 5;
    int lane = threadIdx.x & 31;
    if (t >= T_TOK) return;
    const float* xr = g_xr + (size_t)t * HDIM;
    float acc[8] = {0.f,0.f,0.f,0.f,0.f,0.f,0.f,0.f};
    for (int h = lane; h < HDIM; h += 32) {
        float xv = xr[h];
        float4 w0 = *(const float4*)(gw + (size_t)h * 8);
        float4 w1 = *(const float4*)(gw + (size_t)h * 8 + 4);
        acc[0] += xv * w0.x; acc[1] += xv * w0.y; acc[2] += xv * w0.z; acc[3] += xv * w0.w;
        acc[4] += xv * w1.x; acc[5] += xv * w1.y; acc[6] += xv * w1.z; acc[7] += xv * w1.w;
    }
#pragma unroll
    for (int o = 16; o; o >>= 1)
#pragma unroll
        for (int e = 0; e < 8; e++) acc[e] += __shfl_down_sync(0xffffffffu, acc[e], o);
    if (lane == 0) {
        float mx = acc[0];
#pragma unroll
        for (int e = 1; e < 8; e++) mx = fmaxf(mx, acc[e]);
        float p[8]; float Z = 0.f;
#pragma unroll
        for (int e = 0; e < 8; e++) { p[e] = __expf(acc[e] - mx); Z += p[e]; }
        float rZ = 1.f / Z;
#pragma unroll
        for (int e = 0; e < 8; e++) p[e] *= rZ;
        int i0 = 0; float p0 = p[0];
#pragma unroll
        for (int e = 1; e < 8; e++) if (p[e] > p0) { p0 = p[e]; i0 = e; }
        int i1 = -1; float p1 = -1.f;
#pragma unroll
        for (int e = 0; e < 8; e++) if (e != i0 && p[e] > p1) { p1 = p[e]; i1 = e; }
        float s = 1.f / (p0 + p1 + 1e-5f);
        g_tok_e[2*t] = i0;     g_tok_w[2*t] = p0 * s;
        g_tok_e[2*t+1] = i1;   g_tok_w[2*t+1] = p1 * s;
        atomicAdd(&g_counts[i0], 1); atomicAdd(&g_counts[i1], 1);
    }
}

__global__ void k_offsets() {
    if (threadIdx.x == 0) {
        int s = 0;
        for (int e = 0; e < NEXP; e++) { g_offsets[e] = s; s += g_counts[e]; g_cursor[e] = 0; }
    }
}

__global__ void k_place() {
    int t = blockIdx.x * blockDim.x + threadIdx.x;
    if (t >= T_TOK) return;
#pragma unroll
    for (int k = 0; k < 2; k++) {
        int e = g_tok_e[2*t + k];
        int pos = g_offsets[e] + atomicAdd(&g_cursor[e], 1);
        g_list_tok[pos] = t;
        g_list_w[pos] = g_tok_w[2*t + k];
        g_tok_slot[2*t + k] = pos;
    }
}

__global__ void k_combine(float* __restrict__ out) {
    int gid = blockIdx.x * blockDim.x + threadIdx.x;
    int t = gid / (HDIM / 4);
    int c = (gid % (HDIM / 4)) * 4;
    if (t >= T_TOK) return;
    int s0 = g_tok_slot[2*t], s1 = g_tok_slot[2*t+1];
    float4 o = *(const float4*)(out + (size_t)t * HDIM + c);
    float4 a = *(const float4*)(g_eout + (size_t)s0 * HDIM + c);
    float4 b = *(const float4*)(g_eout + (size_t)s1 * HDIM + c);
    o.x += a.x + b.x; o.y += a.y + b.y; o.z += a.z + b.z; o.w += a.w + b.w;
    *(float4*)(out + (size_t)t * HDIM + c) = o;
}

// ======================= bf16 HMMA GEMM (router only, 4-pass) =======================
#define CH_K    32
#define ROWB    80
#define A_MATB  (256 * ROWB)
#define B_MATB  (128 * ROWB)
#define OFF_AL  A_MATB
#define OFF_BH  (2 * A_MATB)
#define OFF_BL  (2 * A_MATB + B_MATB)
#define STGB    (2 * A_MATB + 2 * B_MATB)
#define NSTG    3
#define GEMM_SMEM (NSTG * STGB)

__global__ __launch_bounds__(512, 1) void k_gemm(
    const bf16* __restrict__ Ah, const bf16* __restrict__ Al,
    const bf16* __restrict__ Bh, const bf16* __restrict__ Bl,
    float* __restrict__ C, int Kdim, int Nld, int Mdense,
    const float* __restrict__ xadd, const float* __restrict__ bias)
{
    const int cnt = Mdense;
    const int m0 = blockIdx.y * 256;
    if (m0 >= cnt) return;
    const int n0 = blockIdx.x * 128;

    extern __shared__ char smem[];
    const u32 sb = smem_u32(smem);
    const int tid = threadIdx.x;
    const int nc = Kdim / CH_K;

#define LOAD_STAGE(c) do {                                                     \
        int _k0 = (c) * CH_K;                                                  \
        u32 _db = sb + ((c) % NSTG) * STGB;                                    \
        if (tid < 256) {                                                       \
            const bf16* _pa = Ah + (size_t)(m0 + tid) * Kdim + _k0;            \
            const bf16* _pl = Al + (size_t)(m0 + tid) * Kdim + _k0;            \
            u32 _da = _db + tid * ROWB;                                        \
            cpa16(_da,      _pa); cpa16(_da + 16, _pa + 8);                    \
            cpa16(_da + 32, _pa + 16); cpa16(_da + 48, _pa + 24);              \
            u32 _dl = _db + OFF_AL + tid * ROWB;                               \
            cpa16(_dl,      _pl); cpa16(_dl + 16, _pl + 8);                    \
            cpa16(_dl + 32, _pl + 16); cpa16(_dl + 48, _pl + 24);              \
        } else if (tid < 384) {                                                \
            int _r = tid - 256;                                                \
            const bf16* _p = Bh + (size_t)(n0 + _r) * Kdim + _k0;              \
            u32 _d = _db + OFF_BH + _r * ROWB;                                 \
            cpa16(_d,      _p); cpa16(_d + 16, _p + 8);                        \
            cpa16(_d + 32, _p + 16); cpa16(_d + 48, _p + 24);                  \
        } else {                                                               \
            int _r = tid - 384;                                                \
            const bf16* _p = Bl + (size_t)(n0 + _r) * Kdim + _k0;              \
            u32 _d = _db + OFF_BL + _r * ROWB;                                 \
            cpa16(_d,      _p); cpa16(_d + 16, _p + 8);                        \
            cpa16(_d + 32, _p + 16); cpa16(_d + 48, _p + 24);                  \
        }                                                                      \
    } while (0)

    float acc[4][4][4];
#pragma unroll
    for (int i = 0; i < 4; i++)
#pragma unroll
        for (int j = 0; j < 4; j++)
#pragma unroll
            for (int q = 0; q < 4; q++) acc[i][j][q] = 0.f;

    const int wid = tid >> 5, lane = tid & 31;
    const int wm = wid >> 2, wn = wid & 3;
    const int fr = lane & 15;
    const int fk = ((lane >> 4) & 1) * 16;

    LOAD_STAGE(0); cpa_commit();
    LOAD_STAGE(1); cpa_commit();

    for (int c = 0; c < nc; c++) {
        if (c < nc - 1) asm volatile("cp.async.wait_group 1;" ::: "memory");
        else            asm volatile("cp.async.wait_group 0;" ::: "memory");
        __syncthreads();
        if (c + 2 < nc) { LOAD_STAGE(c + 2); cpa_commit(); }

        const u32 ab = sb + (c % NSTG) * STGB;
        const u32 bb = ab + OFF_BH;

#pragma unroll
        for (int kk = 0; kk < 2; kk++) {
            const int kb = kk * 32;
            u32 ahf[4][4], alf[4][4], bhf[2][4], blf[2][4];
#pragma unroll
            for (int i = 0; i < 4; i++) {
                u32 ad = ab + (wm * 64 + i * 16 + fr) * ROWB + kb + fk;
                ldsm4(ahf[i], ad);
                ldsm4(alf[i], ad + OFF_AL);
            }
#pragma unroll
            for (int j = 0; j < 2; j++) {
                u32 bd = bb + (wn * 32 + j * 16 + fr) * ROWB + kb + fk;
                ldsm4(bhf[j], bd);
                ldsm4(blf[j], bd + B_MATB);
            }
#pragma unroll
            for (int i = 0; i < 4; i++)
#pragma unroll
                for (int nt = 0; nt < 4; nt++) {
                    int j = nt >> 1, t = nt & 1;
                    float* cc = acc[i][nt];
                    u32 b0h = bhf[j][t], b1h = bhf[j][t + 2];
                    u32 b0l = blf[j][t], b1l = blf[j][t + 2];
                    mma_bf16(cc, ahf[i], b0h, b1h);
                    mma_bf16(cc, ahf[i], b0l, b1l);
                    mma_bf16(cc, alf[i], b0h, b1h);
                    mma_bf16(cc, alf[i], b0l, b1l);
                }
        }
    }

#pragma unroll
    for (int i = 0; i < 4; i++) {
#pragma unroll
        for (int h = 0; h < 2; h++) {
            int lr = wm * 64 + i * 16 + (lane >> 2) + h * 8;
            int orow = m0 + lr;
            float* crow = C + (size_t)orow * Nld + n0 + wn * 32;
            const float* xr = xadd + (size_t)orow * HDIM + n0 + wn * 32;
            const float* bs = bias + n0 + wn * 32;
#pragma unroll
            for (int nt = 0; nt < 4; nt++) {
                int col = nt * 8 + (lane & 3) * 2;
                float v0 = acc[i][nt][h * 2]     + xr[col]     + bs[col];
                float v1 = acc[i][nt][h * 2 + 1] + xr[col + 1] + bs[col + 1];
                *(float2*)(crow + col) = make_float2(v0, v1);
            }
        }
    }
#undef LOAD_STAGE
}

// ======================= fp16 single-pass GEMM =======================
// C = A @ B^T. epi=0: plain fp32 store (row length Nld).
// epi=1: fused SwiGLU epilogue — B rows interleaved (even=gate, odd=up);
//        h = w * silu(gate) * up stored as fp16 at row length Nld/2.
//        w = 1 (mode 0) or g_list_w[slot] (mode 1).
// CTA tile 256x128, 512 threads, K-chunk 32, 4-stage ring.
// mode: 0 dense rows, 1 gathered (token list per expert), 2 slot rows (per expert)
#define QROWB   80
#define QA_MATB (256 * QROWB)
#define QOFF_B  QA_MATB
#define QSTGB   (QA_MATB + 128 * QROWB) // 30720
#define QNSTG   4
#define GEMM16_SMEM (QNSTG * QSTGB)     // 122880

__global__ __launch_bounds__(512, 1) void k_gemm16(
    const __half* __restrict__ A, const __half* __restrict__ B,
    float* __restrict__ Cf, __half* __restrict__ Ch,
    int Kdim, int Nld, int Mdense, int mode, int epi)
{
    int cnt, off;
    if (mode == 0) { cnt = Mdense; off = 0; }
    else {
        int e = blockIdx.z;
        cnt = g_counts[e]; off = g_offsets[e];
        B += (size_t)e * Nld * Kdim;
    }
    const int m0 = blockIdx.y * 256;
    if (m0 >= cnt) return;
    const int n0 = blockIdx.x * 128;

    extern __shared__ char smem[];
    __shared__ int s_arow[256];
    const u32 sb = smem_u32(smem);
    const int tid = threadIdx.x;

    if (tid < 256) {
        int gr;
        if (mode == 0) gr = m0 + tid;
        else {
            int mr = m0 + tid; if (mr > cnt - 1) mr = cnt - 1;
            gr = (mode == 1) ? g_list_tok[off + mr] : (off + mr);
        }
        s_arow[tid] = gr;
    }
    __syncthreads();

    const int nc = Kdim / CH_K;

#define QLOAD(c) do {                                                          \
        int _k0 = (c) * CH_K;                                                  \
        u32 _db = sb + ((c) % QNSTG) * QSTGB;                                  \
        if (tid < 256) {                                                       \
            const __half* _pa = A + (size_t)s_arow[tid] * Kdim + _k0;          \
            u32 _da = _db + tid * QROWB;                                       \
            cpa16(_da,      _pa); cpa16(_da + 16, _pa + 8);                    \
            cpa16(_da + 32, _pa + 16); cpa16(_da + 48, _pa + 24);              \
        } else {                                                               \
            int _r = (tid - 256) >> 1, _h = (tid - 256) & 1;                   \
            const __half* _p = B + (size_t)(n0 + _r) * Kdim + _k0 + _h * 16;   \
            u32 _d = _db + QOFF_B + _r * QROWB + _h * 32;                      \
            cpa16(_d, _p); cpa16(_d + 16, _p + 8);                             \
        }                                                                      \
    } while (0)

    float acc[4][4][4];
#pragma unroll
    for (int i = 0; i < 4; i++)
#pragma unroll
        for (int j = 0; j < 4; j++)
#pragma unroll
            for (int q = 0; q < 4; q++) acc[i][j][q] = 0.f;

    const int wid = tid >> 5, lane = tid & 31;
    const int wm = wid >> 2, wn = wid & 3;
    const int fr = lane & 15;
    const int fk = ((lane >> 4) & 1) * 16;

    QLOAD(0); cpa_commit();
    QLOAD(1); cpa_commit();
    QLOAD(2); cpa_commit();

    for (int c = 0; c < nc; c++) {
        if (c + 2 < nc)      asm volatile("cp.async.wait_group 2;" ::: "memory");
        else if (c + 1 < nc) asm volatile("cp.async.wait_group 1;" ::: "memory");
        else                 asm volatile("cp.async.wait_group 0;" ::: "memory");
        __syncthreads();
        if (c + 3 < nc) { QLOAD(c + 3); cpa_commit(); }

        const u32 ab = sb + (c % QNSTG) * QSTGB;
        const u32 bb = ab + QOFF_B;

#pragma unroll
        for (int kk = 0; kk < 2; kk++) {
            const int kb = kk * 32;
            u32 af[4][4], bf[2][4];
#pragma unroll
            for (int i = 0; i < 4; i++) {
                u32 ad = ab + (wm * 64 + i * 16 + fr) * QROWB + kb + fk;
                ldsm4(af[i], ad);
            }
#pragma unroll
            for (int j = 0; j < 2; j++) {
                u32 bd = bb + (wn * 32 + j * 16 + fr) * QROWB + kb + fk;
                ldsm4(bf[j], bd);
            }
#pragma unroll
            for (int i = 0; i < 4; i++)
#pragma unroll
                for (int nt = 0; nt < 4; nt++) {
                    int j = nt >> 1, t = nt & 1;
                    mma_f16(acc[i][nt], af[i], bf[j][t], bf[j][t + 2]);
                }
        }
    }

#pragma unroll
    for (int i = 0; i < 4; i++) {
#pragma unroll
        for (int h = 0; h < 2; h++) {
            int lr = wm * 64 + i * 16 + (lane >> 2) + h * 8;
            if (m0 + lr < cnt) {
                int orow = (mode == 0 ? 0 : off) + m0 + lr;
                if (epi == 0) {
                    float* crow = Cf + (size_t)orow * Nld + n0 + wn * 32;
#pragma unroll
                    for (int nt = 0; nt < 4; nt++) {
                        int col = nt * 8 + (lane & 3) * 2;
                        *(float2*)(crow + col) =
                            make_float2(acc[i][nt][h * 2], acc[i][nt][h * 2 + 1]);
                    }
                } else {
                    float w = (mode == 0) ? 1.0f : g_list_w[orow];
                    __half* hrow = Ch + (size_t)orow * (Nld / 2) + (n0 + wn * 32) / 2;
#pragma unroll
                    for (int nt = 0; nt < 4; nt++) {
                        int hcol = nt * 4 + (lane & 3);
                        float gv = acc[i][nt][h * 2];
                        float uv = acc[i][nt][h * 2 + 1];
                        float sig = 1.f / (1.f + __expf(-gv));
                        hrow[hcol] = __float2half_rn(w * (gv * sig) * uv);
                    }
                }
            }
        }
    }
#undef QLOAD
}

// ======================= launch =======================
extern "C" void kernel_launch(void* const* d_in, const int* in_sizes, int n_in,
                              void* d_out, int out_size) {
    const float* x   = (const float*)d_in[0];
    const float* tcx = (const float*)d_in[1];
    const float* tpw = (const float*)d_in[2];
    const float* tpb = (const float*)d_in[3];
    const float* gw  = (const float*)d_in[4];
    const float* eg  = (const float*)d_in[5];
    const float* eu  = (const float*)d_in[6];
    const float* ed  = (const float*)d_in[7];
    const float* sg  = (const float*)d_in[8];
    const float* su  = (const float*)d_in[9];
    const float* sd  = (const float*)d_in[10];
    float* out = (float*)d_out;

    cudaFuncSetAttribute(k_gemm, cudaFuncAttributeMaxDynamicSharedMemorySize, GEMM_SMEM);
    cudaFuncSetAttribute(k_gemm16, cudaFuncAttributeMaxDynamicSharedMemorySize, GEMM16_SMEM);

    bf16 *tch, *tcl, *tpwTh, *tpwTl;
    __half *x16, *sguT, *eguT, *sdT16, *edT16, *hs16, *he16;
    float *xr, *eout;
    cudaGetSymbolAddress((void**)&tch, g_tch);   cudaGetSymbolAddress((void**)&tcl, g_tcl);
    cudaGetSymbolAddress((void**)&tpwTh, g_tpwT_h); cudaGetSymbolAddress((void**)&tpwTl, g_tpwT_l);
    cudaGetSymbolAddress((void**)&x16, g_x16);
    cudaGetSymbolAddress((void**)&sguT, g_sguT); cudaGetSymbolAddress((void**)&eguT, g_eguT);
    cudaGetSymbolAddress((void**)&sdT16, g_sdT16); cudaGetSymbolAddress((void**)&edT16, g_edT16);
    cudaGetSymbolAddress((void**)&hs16, g_hs16); cudaGetSymbolAddress((void**)&he16, g_he16);
    cudaGetSymbolAddress((void**)&xr, g_xr);
    cudaGetSymbolAddress((void**)&eout, g_eout);

    dim3 wb(32, 8);
    int n4 = T_TOK * HDIM / 4;

    // 0: x -> fp16
    k_cvt16<<<n4 / 256, 256>>>(x, x16, n4);
    // 1-2: shared gate/up weights, INTERLEAVED rows (even=gate, odd=up)
    k_t16<<<dim3(IDIM/32, HDIM/32, 1), wb>>>(sg, sguT, HDIM, IDIM, 0, 0, 2, 0);
    k_t16<<<dim3(IDIM/32, HDIM/32, 1), wb>>>(su, sguT, HDIM, IDIM, 0, 0, 2, 1);
    // 3: fused shared gate+up GEMM + silu epilogue -> hs16   <== ncu capture target
    k_gemm16<<<dim3(2*IDIM/128, T_TOK/256, 1), 512, GEMM16_SMEM>>>(
        x16, sguT, nullptr, hs16, HDIM, 2*IDIM, T_TOK, 0, 1);
    // 4: counters
    k_init<<<1, 32>>>();
    // 5-7: router (bf16 4-pass, exact top-k)
    k_split<<<n4 / 256, 256>>>(tcx, tch, tcl, n4);
    k_tsplit<<<dim3(HDIM/32, HDIM/32, 1), wb>>>(tpw, tpwTh, tpwTl, HDIM, HDIM);
    k_gemm<<<dim3(HDIM/128, T_TOK/256, 1), 512, GEMM_SMEM>>>(
        tch, tcl, tpwTh, tpwTl, xr, HDIM, HDIM, T_TOK, x, tpb);
    // 8-10: routing
    k_gate<<<T_TOK / 8, 256>>>(gw);
    k_offsets<<<1, 32>>>();
    k_place<<<T_TOK / 256, 256>>>();
    // 11: shared down weights
    k_t16<<<dim3(HDIM/32, IDIM/32, 1), wb>>>(sd, sdT16, IDIM, HDIM, 0, 0, 1, 0);
    // 12: shared down -> out
    k_gemm16<<<dim3(HDIM/128, T_TOK/256, 1), 512, GEMM16_SMEM>>>(
        hs16, sdT16, out, nullptr, IDIM, HDIM, T_TOK, 0, 0);
    // 13-15: expert weights (gate/up interleaved)
    k_t16<<<dim3(IDIM/32, HDIM/32, NEXP), wb>>>(eg, eguT, HDIM, IDIM,
        (size_t)HDIM * IDIM, (size_t)2 * IDIM * HDIM, 2, 0);
    k_t16<<<dim3(IDIM/32, HDIM/32, NEXP), wb>>>(eu, eguT, HDIM, IDIM,
        (size_t)HDIM * IDIM, (size_t)2 * IDIM * HDIM, 2, 1);
    k_t16<<<dim3(HDIM/32, IDIM/32, NEXP), wb>>>(ed, edT16, IDIM, HDIM,
        (size_t)IDIM * HDIM, (size_t)IDIM * HDIM, 1, 0);
    // 16: fused expert gate+up (gathered) + silu epilogue (combine weight folded) -> he16
    k_gemm16<<<dim3(2*IDIM/128, SLOTS/256, NEXP), 512, GEMM16_SMEM>>>(
        x16, eguT, nullptr, he16, HDIM, 2*IDIM, 0, 1, 1);
    // 17: expert down -> per-slot scratch
    k_gemm16<<<dim3(HDIM/128, SLOTS/256, NEXP), 512, GEMM16_SMEM>>>(
        he16, edT16, eout, nullptr, IDIM, HDIM, 0, 2, 0);
    // 18: combine
    k_combine<<<(T_TOK * (HDIM / 4)) / 256, 256>>>(out);
}

// round 13
// speedup vs baseline: 1.1243x; 1.1243x over previous
#include <cuda_runtime.h>
#include <cuda_bf16.h>
#include <cuda_fp16.h>
#include <stdint.h>
#include <math.h>

typedef unsigned long long u64;
typedef unsigned int u32;

#define T_TOK 4096
#define HDIM  1024
#define IDIM  2048
#define NEXP  8
#define SLOTS (2 * T_TOK)

// ======================= scratch (device globals) =======================
// fp16 single-pass path (gate/up weights INTERLEAVED: even row=gate, odd row=up)
__device__ __align__(16) __half g_x16[(size_t)T_TOK * HDIM];
__device__ __align__(16) __half g_sguT[(size_t)(2 * IDIM) * HDIM];
__device__ __align__(16) __half g_eguT[(size_t)NEXP * (2 * IDIM) * HDIM];
__device__ __align__(16) __half g_sdT16[(size_t)HDIM * IDIM];
__device__ __align__(16) __half g_edT16[(size_t)NEXP * HDIM * IDIM];
__device__ __align__(16) __half g_hs16[(size_t)T_TOK * IDIM];
__device__ __align__(16) __half g_he16[(size_t)SLOTS * IDIM];

__device__ float g_eout[(size_t)SLOTS * HDIM];

// router folding
__device__ float g_w2[HDIM * NEXP];      // tpw @ gw
__device__ float g_bconst[NEXP];         // tpb @ gw

// routing
__device__ int   g_tok_e[T_TOK * 2];
__device__ float g_tok_w[T_TOK * 2];
__device__ int   g_tok_slot[T_TOK * 2];
__device__ int   g_counts[NEXP];
__device__ int   g_offsets[NEXP];
__device__ int   g_cursor[NEXP];
__device__ int   g_list_tok[SLOTS];
__device__ float g_list_w[SLOTS];

// ======================= PTX helpers (sm_80-era, compute_103-safe) =======================
__device__ __forceinline__ u32 smem_u32(const void* p) {
    u32 a;
    asm("{ .reg .u64 t; cvta.to.shared.u64 t, %1; cvt.u32.u64 %0, t; }" : "=r"(a) : "l"(p));
    return a;
}
__device__ __forceinline__ void cpa16(u32 dst, const void* src) {
    asm volatile("cp.async.cg.shared.global [%0], [%1], 16;"
                 :: "r"(dst), "l"(src) : "memory");
}
__device__ __forceinline__ void cpa_commit() {
    asm volatile("cp.async.commit_group;" ::: "memory");
}
__device__ __forceinline__ void ldsm4(u32* r, u32 addr) {
    asm volatile("ldmatrix.sync.aligned.m8n8.x4.shared.b16 {%0,%1,%2,%3}, [%4];"
                 : "=r"(r[0]), "=r"(r[1]), "=r"(r[2]), "=r"(r[3]) : "r"(addr));
}
__device__ __forceinline__ void mma_f16(float* c, const u32* a, u32 b0, u32 b1) {
    asm volatile("mma.sync.aligned.m16n8k16.row.col.f32.f16.f16.f32 "
                 "{%0,%1,%2,%3}, {%4,%5,%6,%7}, {%8,%9}, {%0,%1,%2,%3};"
                 : "+f"(c[0]), "+f"(c[1]), "+f"(c[2]), "+f"(c[3])
                 : "r"(a[0]), "r"(a[1]), "r"(a[2]), "r"(a[3]), "r"(b0), "r"(b1));
}

// ======================= small kernels =======================
__global__ void k_init() {
    int i = threadIdx.x;
    if (i < NEXP) { g_counts[i] = 0; g_cursor[i] = 0; }
}

// fp32 -> fp16 (single limb)
__global__ void k_cvt16(const float* __restrict__ S, __half* __restrict__ H, int n4) {
    int i = blockIdx.x * blockDim.x + threadIdx.x;
    if (i >= n4) return;
    float4 v = ((const float4*)S)[i];
    union { __half b[4]; uint2 u; } uh;
    uh.b[0] = __float2half_rn(v.x); uh.b[1] = __float2half_rn(v.y);
    uh.b[2] = __float2half_rn(v.z); uh.b[3] = __float2half_rn(v.w);
    ((uint2*)H)[i] = uh.u;
}

// transpose + single fp16: W [K,N] (+z*srcZ) -> T rows (n*rowmul + phase) (+z*dstZ)
__global__ void k_t16(const float* __restrict__ W, __half* __restrict__ T,
                      int K, int N, size_t srcZ, size_t dstZ, int rowmul, int phase) {
    W += (size_t)blockIdx.z * srcZ; T += (size_t)blockIdx.z * dstZ;
    __shared__ float t[32][33];
    int k0 = blockIdx.y * 32, n0 = blockIdx.x * 32;
    int tx = threadIdx.x, ty = threadIdx.y;
#pragma unroll
    for (int q = 0; q < 4; q++)
        t[ty + 8 * q][tx] = W[(size_t)(k0 + ty + 8 * q) * N + n0 + tx];
    __syncthreads();
#pragma unroll
    for (int q = 0; q < 4; q++) {
        int n = ty + 8 * q;
        T[(size_t)((n0 + n) * rowmul + phase) * K + k0 + tx] = __float2half_rn(t[tx][n]);
    }
}

// W2[h,e] = sum_k tpw[h,k] * gw[k,e]   (one warp per row h)
__global__ void k_w2(const float* __restrict__ tpw, const float* __restrict__ gw) {
    int h = (blockIdx.x * blockDim.x + threadIdx.x) >> 5;
    int lane = threadIdx.x & 31;
    if (h >= HDIM) return;
    const float* row = tpw + (size_t)h * HDIM;
    float acc[8] = {0.f,0.f,0.f,0.f,0.f,0.f,0.f,0.f};
    for (int k = lane; k < HDIM; k += 32) {
        float v = row[k];
        float4 w0 = *(const float4*)(gw + (size_t)k * 8);
        float4 w1 = *(const float4*)(gw + (size_t)k * 8 + 4);
        acc[0] += v * w0.x; acc[1] += v * w0.y; acc[2] += v * w0.z; acc[3] += v * w0.w;
        acc[4] += v * w1.x; acc[5] += v * w1.y; acc[6] += v * w1.z; acc[7] += v * w1.w;
    }
#pragma unroll
    for (int o = 16; o; o >>= 1)
#pragma unroll
        for (int e = 0; e < 8; e++) acc[e] += __shfl_down_sync(0xffffffffu, acc[e], o);
    if (lane == 0) {
#pragma unroll
        for (int e = 0; e < 8; e++) g_w2[h * 8 + e] = acc[e];
    }
}

// bconst[e] = sum_h tpb[h] * gw[h,e]
__global__ void k_bconst(const float* __restrict__ tpb, const float* __restrict__ gw) {
    __shared__ float red[256][8];
    int tid = threadIdx.x;
    float acc[8] = {0.f,0.f,0.f,0.f,0.f,0.f,0.f,0.f};
    for (int h = tid; h < HDIM; h += 256) {
        float b = tpb[h];
        float4 w0 = *(const float4*)(gw + (size_t)h * 8);
        float4 w1 = *(const float4*)(gw + (size_t)h * 8 + 4);
        acc[0] += b * w0.x; acc[1] += b * w0.y; acc[2] += b * w0.z; acc[3] += b * w0.w;
        acc[4] += b * w1.x; acc[5] += b * w1.y; acc[6] += b * w1.z; acc[7] += b * w1.w;
    }
#pragma unroll
    for (int e = 0; e < 8; e++) red[tid][e] = acc[e];
    __syncthreads();
    for (int s = 128; s; s >>= 1) {
        if (tid < s)
#pragma unroll
            for (int e = 0; e < 8; e++) red[tid][e] += red[tid + s][e];
        __syncthreads();
    }
    if (tid < 8) g_bconst[tid] = red[0][tid];
}

// fused gate: logits[t] = x[t]@gw + tc[t]@W2 + bconst; softmax; top-2; histogram
__global__ void k_gate(const float* __restrict__ x, const float* __restrict__ tcx,
                       const float* __restrict__ gw) {
    int t = (blockIdx.x * blockDim.x + threadIdx.x) >> 5;
    int lane = threadIdx.x & 31;
    if (t >= T_TOK) return;
    const float* xr = x + (size_t)t * HDIM;
    const float* tr = tcx + (size_t)t * HDIM;
    float acc[8] = {0.f,0.f,0.f,0.f,0.f,0.f,0.f,0.f};
    for (int h = lane; h < HDIM; h += 32) {
        float xv = xr[h];
        float tv = tr[h];
        float4 w0 = *(const float4*)(gw + (size_t)h * 8);
        float4 w1 = *(const float4*)(gw + (size_t)h * 8 + 4);
        float4 m0 = *(const float4*)(g_w2 + (size_t)h * 8);
        float4 m1 = *(const float4*)(g_w2 + (size_t)h * 8 + 4);
        acc[0] += xv * w0.x + tv * m0.x; acc[1] += xv * w0.y + tv * m0.y;
        acc[2] += xv * w0.z + tv * m0.z; acc[3] += xv * w0.w + tv * m0.w;
        acc[4] += xv * w1.x + tv * m1.x; acc[5] += xv * w1.y + tv * m1.y;
        acc[6] += xv * w1.z + tv * m1.z; acc[7] += xv * w1.w + tv * m1.w;
    }
#pragma unroll
    for (int o = 16; o; o >>= 1)
#pragma unroll
        for (int e = 0; e < 8; e++) acc[e] += __shfl_down_sync(0xffffffffu, acc[e], o);
    if (lane == 0) {
#pragma unroll
        for (int e = 0; e < 8; e++) acc[e] += g_bconst[e];
        float mx = acc[0];
#pragma unroll
        for (int e = 1; e < 8; e++) mx = fmaxf(mx, acc[e]);
        float p[8]; float Z = 0.f;
#pragma unroll
        for (int e = 0; e < 8; e++) { p[e] = __expf(acc[e] - mx); Z += p[e]; }
        float rZ = 1.f / Z;
#pragma unroll
        for (int e = 0; e < 8; e++) p[e] *= rZ;
        int i0 = 0; float p0 = p[0];
#pragma unroll
        for (int e = 1; e < 8; e++) if (p[e] > p0) { p0 = p[e]; i0 = e; }
        int i1 = -1; float p1 = -1.f;
#pragma unroll
        for (int e = 0; e < 8; e++) if (e != i0 && p[e] > p1) { p1 = p[e]; i1 = e; }
        float s = 1.f / (p0 + p1 + 1e-5f);
        g_tok_e[2*t] = i0;     g_tok_w[2*t] = p0 * s;
        g_tok_e[2*t+1] = i1;   g_tok_w[2*t+1] = p1 * s;
        atomicAdd(&g_counts[i0], 1); atomicAdd(&g_counts[i1], 1);
    }
}

__global__ void k_offsets() {
    if (threadIdx.x == 0) {
        int s = 0;
        for (int e = 0; e < NEXP; e++) { g_offsets[e] = s; s += g_counts[e]; g_cursor[e] = 0; }
    }
}

__global__ void k_place() {
    int t = blockIdx.x * blockDim.x + threadIdx.x;
    if (t >= T_TOK) return;
#pragma unroll
    for (int k = 0; k < 2; k++) {
        int e = g_tok_e[2*t + k];
        int pos = g_offsets[e] + atomicAdd(&g_cursor[e], 1);
        g_list_tok[pos] = t;
        g_list_w[pos] = g_tok_w[2*t + k];
        g_tok_slot[2*t + k] = pos;
    }
}

__global__ void k_combine(float* __restrict__ out) {
    int gid = blockIdx.x * blockDim.x + threadIdx.x;
    int t = gid / (HDIM / 4);
    int c = (gid % (HDIM / 4)) * 4;
    if (t >= T_TOK) return;
    int s0 = g_tok_slot[2*t], s1 = g_tok_slot[2*t+1];
    float4 o = *(const float4*)(out + (size_t)t * HDIM + c);
    float4 a = *(const float4*)(g_eout + (size_t)s0 * HDIM + c);
    float4 b = *(const float4*)(g_eout + (size_t)s1 * HDIM + c);
    o.x += a.x + b.x; o.y += a.y + b.y; o.z += a.z + b.z; o.w += a.w + b.w;
    *(float4*)(out + (size_t)t * HDIM + c) = o;
}

// ======================= fp16 single-pass GEMM =======================
// C = A @ B^T. epi=0: plain fp32 store (row length Nld).
// epi=1: fused SwiGLU epilogue — B rows interleaved (even=gate, odd=up);
//        h = w * silu(gate) * up stored as fp16 at row length Nld/2.
// CTA tile 256x128, 512 threads, K-chunk 32, 4-stage ring.
// mode: 0 dense rows, 1 gathered (token list per expert), 2 slot rows (per expert)
#define CH_K    32
#define QROWB   80
#define QA_MATB (256 * QROWB)
#define QOFF_B  QA_MATB
#define QSTGB   (QA_MATB + 128 * QROWB) // 30720
#define QNSTG   4
#define GEMM16_SMEM (QNSTG * QSTGB)     // 122880

__global__ __launch_bounds__(512, 1) void k_gemm16(
    const __half* __restrict__ A, const __half* __restrict__ B,
    float* __restrict__ Cf, __half* __restrict__ Ch,
    int Kdim, int Nld, int Mdense, int mode, int epi)
{
    int cnt, off;
    if (mode == 0) { cnt = Mdense; off = 0; }
    else {
        int e = blockIdx.z;
        cnt = g_counts[e]; off = g_offsets[e];
        B += (size_t)e * Nld * Kdim;
    }
    const int m0 = blockIdx.y * 256;
    if (m0 >= cnt) return;
    const int n0 = blockIdx.x * 128;

    extern __shared__ char smem[];
    __shared__ int s_arow[256];
    const u32 sb = smem_u32(smem);
    const int tid = threadIdx.x;

    if (tid < 256) {
        int gr;
        if (mode == 0) gr = m0 + tid;
        else {
            int mr = m0 + tid; if (mr > cnt - 1) mr = cnt - 1;
            gr = (mode == 1) ? g_list_tok[off + mr] : (off + mr);
        }
        s_arow[tid] = gr;
    }
    __syncthreads();

    const int nc = Kdim / CH_K;

#define QLOAD(c) do {                                                          \
        int _k0 = (c) * CH_K;                                                  \
        u32 _db = sb + ((c) % QNSTG) * QSTGB;                                  \
        if (tid < 256) {                                                       \
            const __half* _pa = A + (size_t)s_arow[tid] * Kdim + _k0;          \
            u32 _da = _db + tid * QROWB;                                       \
            cpa16(_da,      _pa); cpa16(_da + 16, _pa + 8);                    \
            cpa16(_da + 32, _pa + 16); cpa16(_da + 48, _pa + 24);              \
        } else {                                                               \
            int _r = (tid - 256) >> 1, _h = (tid - 256) & 1;                   \
            const __half* _p = B + (size_t)(n0 + _r) * Kdim + _k0 + _h * 16;   \
            u32 _d = _db + QOFF_B + _r * QROWB + _h * 32;                      \
            cpa16(_d, _p); cpa16(_d + 16, _p + 8);                             \
        }                                                                      \
    } while (0)

    float acc[4][4][4];
#pragma unroll
    for (int i = 0; i < 4; i++)
#pragma unroll
        for (int j = 0; j < 4; j++)
#pragma unroll
            for (int q = 0; q < 4; q++) acc[i][j][q] = 0.f;

    const int wid = tid >> 5, lane = tid & 31;
    const int wm = wid >> 2, wn = wid & 3;
    const int fr = lane & 15;
    const int fk = ((lane >> 4) & 1) * 16;

    QLOAD(0); cpa_commit();
    QLOAD(1); cpa_commit();
    QLOAD(2); cpa_commit();

    for (int c = 0; c < nc; c++) {
        if (c + 2 < nc)      asm volatile("cp.async.wait_group 2;" ::: "memory");
        else if (c + 1 < nc) asm volatile("cp.async.wait_group 1;" ::: "memory");
        else                 asm volatile("cp.async.wait_group 0;" ::: "memory");
        __syncthreads();
        if (c + 3 < nc) { QLOAD(c + 3); cpa_commit(); }

        const u32 ab = sb + (c % QNSTG) * QSTGB;
        const u32 bb = ab + QOFF_B;

#pragma unroll
        for (int kk = 0; kk < 2; kk++) {
            const int kb = kk * 32;
            u32 af[4][4], bf[2][4];
#pragma unroll
            for (int i = 0; i < 4; i++) {
                u32 ad = ab + (wm * 64 + i * 16 + fr) * QROWB + kb + fk;
                ldsm4(af[i], ad);
            }
#pragma unroll
            for (int j = 0; j < 2; j++) {
                u32 bd = bb + (wn * 32 + j * 16 + fr) * QROWB + kb + fk;
                ldsm4(bf[j], bd);
            }
#pragma unroll
            for (int i = 0; i < 4; i++)
#pragma unroll
                for (int nt = 0; nt < 4; nt++) {
                    int j = nt >> 1, t = nt & 1;
                    mma_f16(acc[i][nt], af[i], bf[j][t], bf[j][t + 2]);
                }
        }
    }

#pragma unroll
    for (int i = 0; i < 4; i++) {
#pragma unroll
        for (int h = 0; h < 2; h++) {
            int lr = wm * 64 + i * 16 + (lane >> 2) + h * 8;
            if (m0 + lr < cnt) {
                int orow = (mode == 0 ? 0 : off) + m0 + lr;
                if (epi == 0) {
                    float* crow = Cf + (size_t)orow * Nld + n0 + wn * 32;
#pragma unroll
                    for (int nt = 0; nt < 4; nt++) {
                        int col = nt * 8 + (lane & 3) * 2;
                        *(float2*)(crow + col) =
                            make_float2(acc[i][nt][h * 2], acc[i][nt][h * 2 + 1]);
                    }
                } else {
                    float w = (mode == 0) ? 1.0f : g_list_w[orow];
                    __half* hrow = Ch + (size_t)orow * (Nld / 2) + (n0 + wn * 32) / 2;
#pragma unroll
                    for (int nt = 0; nt < 4; nt++) {
                        int hcol = nt * 4 + (lane & 3);
                        float gv = acc[i][nt][h * 2];
                        float uv = acc[i][nt][h * 2 + 1];
                        float sig = 1.f / (1.f + __expf(-gv));
                        hrow[hcol] = __float2half_rn(w * (gv * sig) * uv);
                    }
                }
            }
        }
    }
#undef QLOAD
}

// ======================= launch =======================
extern "C" void kernel_launch(void* const* d_in, const int* in_sizes, int n_in,
                              void* d_out, int out_size) {
    const float* x   = (const float*)d_in[0];
    const float* tcx = (const float*)d_in[1];
    const float* tpw = (const float*)d_in[2];
    const float* tpb = (const float*)d_in[3];
    const float* gw  = (const float*)d_in[4];
    const float* eg  = (const float*)d_in[5];
    const float* eu  = (const float*)d_in[6];
    const float* ed  = (const float*)d_in[7];
    const float* sg  = (const float*)d_in[8];
    const float* su  = (const float*)d_in[9];
    const float* sd  = (const float*)d_in[10];
    float* out = (float*)d_out;

    cudaFuncSetAttribute(k_gemm16, cudaFuncAttributeMaxDynamicSharedMemorySize, GEMM16_SMEM);

    __half *x16, *sguT, *eguT, *sdT16, *edT16, *hs16, *he16;
    float *eout;
    cudaGetSymbolAddress((void**)&x16, g_x16);
    cudaGetSymbolAddress((void**)&sguT, g_sguT); cudaGetSymbolAddress((void**)&eguT, g_eguT);
    cudaGetSymbolAddress((void**)&sdT16, g_sdT16); cudaGetSymbolAddress((void**)&edT16, g_edT16);
    cudaGetSymbolAddress((void**)&hs16, g_hs16); cudaGetSymbolAddress((void**)&he16, g_he16);
    cudaGetSymbolAddress((void**)&eout, g_eout);

    dim3 wb(32, 8);
    int n4 = T_TOK * HDIM / 4;

    // 0: x -> fp16
    k_cvt16<<<n4 / 256, 256>>>(x, x16, n4);
    // 1-2: shared gate/up weights, INTERLEAVED rows (even=gate, odd=up)
    k_t16<<<dim3(IDIM/32, HDIM/32, 1), wb>>>(sg, sguT, HDIM, IDIM, 0, 0, 2, 0);
    k_t16<<<dim3(IDIM/32, HDIM/32, 1), wb>>>(su, sguT, HDIM, IDIM, 0, 0, 2, 1);
    // 3: fused shared gate+up GEMM + silu epilogue -> hs16   <== ncu capture target
    k_gemm16<<<dim3(2*IDIM/128, T_TOK/256, 1), 512, GEMM16_SMEM>>>(
        x16, sguT, nullptr, hs16, HDIM, 2*IDIM, T_TOK, 0, 1);
    // 4: counters
    k_init<<<1, 32>>>();
    // 5-6: router folding (tiny fp32)
    k_w2<<<HDIM / 8, 256>>>(tpw, gw);
    k_bconst<<<1, 256>>>(tpb, gw);
    // 7-9: routing
    k_gate<<<T_TOK / 8, 256>>>(x, tcx, gw);
    k_offsets<<<1, 32>>>();
    k_place<<<T_TOK / 256, 256>>>();
    // 10: shared down weights
    k_t16<<<dim3(HDIM/32, IDIM/32, 1), wb>>>(sd, sdT16, IDIM, HDIM, 0, 0, 1, 0);
    // 11: shared down -> out
    k_gemm16<<<dim3(HDIM/128, T_TOK/256, 1), 512, GEMM16_SMEM>>>(
        hs16, sdT16, out, nullptr, IDIM, HDIM, T_TOK, 0, 0);
    // 12-14: expert weights (gate/up interleaved)
    k_t16<<<dim3(IDIM/32, HDIM/32, NEXP), wb>>>(eg, eguT, HDIM, IDIM,
        (size_t)HDIM * IDIM, (size_t)2 * IDIM * HDIM, 2, 0);
    k_t16<<<dim3(IDIM/32, HDIM/32, NEXP), wb>>>(eu, eguT, HDIM, IDIM,
        (size_t)HDIM * IDIM, (size_t)2 * IDIM * HDIM, 2, 1);
    k_t16<<<dim3(HDIM/32, IDIM/32, NEXP), wb>>>(ed, edT16, IDIM, HDIM,
        (size_t)IDIM * HDIM, (size_t)IDIM * HDIM, 1, 0);
    // 15: fused expert gate+up (gathered) + silu epilogue (combine weight folded) -> he16
    k_gemm16<<<dim3(2*IDIM/128, SLOTS/256, NEXP), 512, GEMM16_SMEM>>>(
        x16, eguT, nullptr, he16, HDIM, 2*IDIM, 0, 1, 1);
    // 16: expert down -> per-slot scratch
    k_gemm16<<<dim3(HDIM/128, SLOTS/256, NEXP), 512, GEMM16_SMEM>>>(
        he16, edT16, eout, nullptr, IDIM, HDIM, 0, 2, 0);
    // 17: combine
    k_combine<<<(T_TOK * (HDIM / 4)) / 256, 256>>>(out);
}

// round 14
// speedup vs baseline: 1.1622x; 1.0338x over previous
#include <cuda_runtime.h>
#include <cuda_bf16.h>
#include <cuda_fp16.h>
#include <stdint.h>
#include <math.h>

typedef unsigned long long u64;
typedef unsigned int u32;

#define T_TOK 4096
#define HDIM  1024
#define IDIM  2048
#define NEXP  8
#define SLOTS (2 * T_TOK)

// ======================= scratch (device globals) =======================
__device__ __align__(16) __half g_x16[(size_t)T_TOK * HDIM];
__device__ __align__(16) __half g_sguT[(size_t)(2 * IDIM) * HDIM];
__device__ __align__(16) __half g_eguT[(size_t)NEXP * (2 * IDIM) * HDIM];
__device__ __align__(16) __half g_sdT16[(size_t)HDIM * IDIM];
__device__ __align__(16) __half g_edT16[(size_t)NEXP * HDIM * IDIM];
__device__ __align__(16) __half g_hs16[(size_t)T_TOK * IDIM];
__device__ __align__(16) __half g_he16[(size_t)SLOTS * IDIM];

__device__ float g_eout[(size_t)SLOTS * HDIM];

// router folding
__device__ float g_w2[HDIM * NEXP];      // tpw @ gw
__device__ float g_bconst[NEXP];         // tpb @ gw

// routing
__device__ int   g_tok_e[T_TOK * 2];
__device__ float g_tok_w[T_TOK * 2];
__device__ int   g_tok_slot[T_TOK * 2];
__device__ int   g_counts[NEXP];
__device__ int   g_offsets[NEXP];
__device__ int   g_cursor[NEXP];
__device__ int   g_list_tok[SLOTS];
__device__ float g_list_w[SLOTS];

// ======================= PTX helpers (sm_80-era, compute_103-safe) =======================
__device__ __forceinline__ u32 smem_u32(const void* p) {
    u32 a;
    asm("{ .reg .u64 t; cvta.to.shared.u64 t, %1; cvt.u32.u64 %0, t; }" : "=r"(a) : "l"(p));
    return a;
}
__device__ __forceinline__ void cpa16(u32 dst, const void* src) {
    asm volatile("cp.async.cg.shared.global [%0], [%1], 16;"
                 :: "r"(dst), "l"(src) : "memory");
}
__device__ __forceinline__ void cpa_commit() {
    asm volatile("cp.async.commit_group;" ::: "memory");
}
__device__ __forceinline__ void ldsm4(u32* r, u32 addr) {
    asm volatile("ldmatrix.sync.aligned.m8n8.x4.shared.b16 {%0,%1,%2,%3}, [%4];"
                 : "=r"(r[0]), "=r"(r[1]), "=r"(r[2]), "=r"(r[3]) : "r"(addr));
}
__device__ __forceinline__ void mma_f16(float* c, const u32* a, u32 b0, u32 b1) {
    asm volatile("mma.sync.aligned.m16n8k16.row.col.f32.f16.f16.f32 "
                 "{%0,%1,%2,%3}, {%4,%5,%6,%7}, {%8,%9}, {%0,%1,%2,%3};"
                 : "+f"(c[0]), "+f"(c[1]), "+f"(c[2]), "+f"(c[3])
                 : "r"(a[0]), "r"(a[1]), "r"(a[2]), "r"(a[3]), "r"(b0), "r"(b1));
}

// ======================= small kernels =======================
__global__ void k_init() {
    int i = threadIdx.x;
    if (i < NEXP) { g_counts[i] = 0; g_cursor[i] = 0; }
}

__global__ void k_cvt16(const float* __restrict__ S, __half* __restrict__ H, int n4) {
    int i = blockIdx.x * blockDim.x + threadIdx.x;
    if (i >= n4) return;
    float4 v = ((const float4*)S)[i];
    union { __half b[4]; uint2 u; } uh;
    uh.b[0] = __float2half_rn(v.x); uh.b[1] = __float2half_rn(v.y);
    uh.b[2] = __float2half_rn(v.z); uh.b[3] = __float2half_rn(v.w);
    ((uint2*)H)[i] = uh.u;
}

// transpose + single fp16: W [K,N] (+z*srcZ) -> T rows (n*rowmul + phase) (+z*dstZ)
__global__ void k_t16(const float* __restrict__ W, __half* __restrict__ T,
                      int K, int N, size_t srcZ, size_t dstZ, int rowmul, int phase) {
    W += (size_t)blockIdx.z * srcZ; T += (size_t)blockIdx.z * dstZ;
    __shared__ float t[32][33];
    int k0 = blockIdx.y * 32, n0 = blockIdx.x * 32;
    int tx = threadIdx.x, ty = threadIdx.y;
#pragma unroll
    for (int q = 0; q < 4; q++)
        t[ty + 8 * q][tx] = W[(size_t)(k0 + ty + 8 * q) * N + n0 + tx];
    __syncthreads();
#pragma unroll
    for (int q = 0; q < 4; q++) {
        int n = ty + 8 * q;
        T[(size_t)((n0 + n) * rowmul + phase) * K + k0 + tx] = __float2half_rn(t[tx][n]);
    }
}

// W2[h,e] = sum_k tpw[h,k] * gw[k,e]
__global__ void k_w2(const float* __restrict__ tpw, const float* __restrict__ gw) {
    int h = (blockIdx.x * blockDim.x + threadIdx.x) >> 5;
    int lane = threadIdx.x & 31;
    if (h >= HDIM) return;
    const float* row = tpw + (size_t)h * HDIM;
    float acc[8] = {0.f,0.f,0.f,0.f,0.f,0.f,0.f,0.f};
    for (int k = lane; k < HDIM; k += 32) {
        float v = row[k];
        float4 w0 = *(const float4*)(gw + (size_t)k * 8);
        float4 w1 = *(const float4*)(gw + (size_t)k * 8 + 4);
        acc[0] += v * w0.x; acc[1] += v * w0.y; acc[2] += v * w0.z; acc[3] += v * w0.w;
        acc[4] += v * w1.x; acc[5] += v * w1.y; acc[6] += v * w1.z; acc[7] += v * w1.w;
    }
#pragma unroll
    for (int o = 16; o; o >>= 1)
#pragma unroll
        for (int e = 0; e < 8; e++) acc[e] += __shfl_down_sync(0xffffffffu, acc[e], o);
    if (lane == 0) {
#pragma unroll
        for (int e = 0; e < 8; e++) g_w2[h * 8 + e] = acc[e];
    }
}

// bconst[e] = sum_h tpb[h] * gw[h,e]
__global__ void k_bconst(const float* __restrict__ tpb, const float* __restrict__ gw) {
    __shared__ float red[256][8];
    int tid = threadIdx.x;
    float acc[8] = {0.f,0.f,0.f,0.f,0.f,0.f,0.f,0.f};
    for (int h = tid; h < HDIM; h += 256) {
        float b = tpb[h];
        float4 w0 = *(const float4*)(gw + (size_t)h * 8);
        float4 w1 = *(const float4*)(gw + (size_t)h * 8 + 4);
        acc[0] += b * w0.x; acc[1] += b * w0.y; acc[2] += b * w0.z; acc[3] += b * w0.w;
        acc[4] += b * w1.x; acc[5] += b * w1.y; acc[6] += b * w1.z; acc[7] += b * w1.w;
    }
#pragma unroll
    for (int e = 0; e < 8; e++) red[tid][e] = acc[e];
    __syncthreads();
    for (int s = 128; s; s >>= 1) {
        if (tid < s)
#pragma unroll
            for (int e = 0; e < 8; e++) red[tid][e] += red[tid + s][e];
        __syncthreads();
    }
    if (tid < 8) g_bconst[tid] = red[0][tid];
}

// fused gate: logits = x@gw + tc@W2 + bconst; softmax; top-2; histogram
__global__ void k_gate(const float* __restrict__ x, const float* __restrict__ tcx,
                       const float* __restrict__ gw) {
    int t = (blockIdx.x * blockDim.x + threadIdx.x) >> 5;
    int lane = threadIdx.x & 31;
    if (t >= T_TOK) return;
    const float* xr = x + (size_t)t * HDIM;
    const float* tr = tcx + (size_t)t * HDIM;
    float acc[8] = {0.f,0.f,0.f,0.f,0.f,0.f,0.f,0.f};
    for (int h = lane; h < HDIM; h += 32) {
        float xv = xr[h];
        float tv = tr[h];
        float4 w0 = *(const float4*)(gw + (size_t)h * 8);
        float4 w1 = *(const float4*)(gw + (size_t)h * 8 + 4);
        float4 m0 = *(const float4*)(g_w2 + (size_t)h * 8);
        float4 m1 = *(const float4*)(g_w2 + (size_t)h * 8 + 4);
        acc[0] += xv * w0.x + tv * m0.x; acc[1] += xv * w0.y + tv * m0.y;
        acc[2] += xv * w0.z + tv * m0.z; acc[3] += xv * w0.w + tv * m0.w;
        acc[4] += xv * w1.x + tv * m1.x; acc[5] += xv * w1.y + tv * m1.y;
        acc[6] += xv * w1.z + tv * m1.z; acc[7] += xv * w1.w + tv * m1.w;
    }
#pragma unroll
    for (int o = 16; o; o >>= 1)
#pragma unroll
        for (int e = 0; e < 8; e++) acc[e] += __shfl_down_sync(0xffffffffu, acc[e], o);
    if (lane == 0) {
#pragma unroll
        for (int e = 0; e < 8; e++) acc[e] += g_bconst[e];
        float mx = acc[0];
#pragma unroll
        for (int e = 1; e < 8; e++) mx = fmaxf(mx, acc[e]);
        float p[8]; float Z = 0.f;
#pragma unroll
        for (int e = 0; e < 8; e++) { p[e] = __expf(acc[e] - mx); Z += p[e]; }
        float rZ = 1.f / Z;
#pragma unroll
        for (int e = 0; e < 8; e++) p[e] *= rZ;
        int i0 = 0; float p0 = p[0];
#pragma unroll
        for (int e = 1; e < 8; e++) if (p[e] > p0) { p0 = p[e]; i0 = e; }
        int i1 = -1; float p1 = -1.f;
#pragma unroll
        for (int e = 0; e < 8; e++) if (e != i0 && p[e] > p1) { p1 = p[e]; i1 = e; }
        float s = 1.f / (p0 + p1 + 1e-5f);
        g_tok_e[2*t] = i0;     g_tok_w[2*t] = p0 * s;
        g_tok_e[2*t+1] = i1;   g_tok_w[2*t+1] = p1 * s;
        atomicAdd(&g_counts[i0], 1); atomicAdd(&g_counts[i1], 1);
    }
}

__global__ void k_offsets() {
    if (threadIdx.x == 0) {
        int s = 0;
        for (int e = 0; e < NEXP; e++) { g_offsets[e] = s; s += g_counts[e]; g_cursor[e] = 0; }
    }
}

__global__ void k_place() {
    int t = blockIdx.x * blockDim.x + threadIdx.x;
    if (t >= T_TOK) return;
#pragma unroll
    for (int k = 0; k < 2; k++) {
        int e = g_tok_e[2*t + k];
        int pos = g_offsets[e] + atomicAdd(&g_cursor[e], 1);
        g_list_tok[pos] = t;
        g_list_w[pos] = g_tok_w[2*t + k];
        g_tok_slot[2*t + k] = pos;
    }
}

__global__ void k_combine(float* __restrict__ out) {
    int gid = blockIdx.x * blockDim.x + threadIdx.x;
    int t = gid / (HDIM / 4);
    int c = (gid % (HDIM / 4)) * 4;
    if (t >= T_TOK) return;
    int s0 = g_tok_slot[2*t], s1 = g_tok_slot[2*t+1];
    float4 o = *(const float4*)(out + (size_t)t * HDIM + c);
    float4 a = *(const float4*)(g_eout + (size_t)s0 * HDIM + c);
    float4 b = *(const float4*)(g_eout + (size_t)s1 * HDIM + c);
    o.x += a.x + b.x; o.y += a.y + b.y; o.z += a.z + b.z; o.w += a.w + b.w;
    *(float4*)(out + (size_t)t * HDIM + c) = o;
}

// ======================= fp16 single-pass GEMM =======================
// C = A @ B^T. epi=0: plain fp32 store. epi=1: fused SwiGLU epilogue
// (B rows interleaved even=gate/odd=up; h=w*silu(g)*u stored fp16 at Nld/2).
// CTA 256x128, 512 threads, K-chunk 32, 4-stage ring.
// mode: 0 dense, 1 gathered tokens per expert, 2 slot rows per expert
#define CH_K    32
#define QROWB   80
#define QA_MATB (256 * QROWB)
#define QOFF_B  QA_MATB
#define QSTGB   (QA_MATB + 128 * QROWB) // 30720
#define QNSTG   4
#define GEMM16_SMEM (QNSTG * QSTGB)     // 122880

__global__ __launch_bounds__(512, 1) void k_gemm16(
    const __half* __restrict__ A, const __half* __restrict__ B,
    float* __restrict__ Cf, __half* __restrict__ Ch,
    int Kdim, int Nld, int Mdense, int mode, int epi)
{
    int cnt, off;
    if (mode == 0) { cnt = Mdense; off = 0; }
    else {
        int e = blockIdx.z;
        cnt = g_counts[e]; off = g_offsets[e];
        B += (size_t)e * Nld * Kdim;
    }
    const int m0 = blockIdx.y * 256;
    if (m0 >= cnt) return;
    const int n0 = blockIdx.x * 128;

    extern __shared__ char smem[];
    __shared__ int s_arow[256];
    const u32 sb = smem_u32(smem);
    const int tid = threadIdx.x;

    if (tid < 256) {
        int gr;
        if (mode == 0) gr = m0 + tid;
        else {
            int mr = m0 + tid; if (mr > cnt - 1) mr = cnt - 1;
            gr = (mode == 1) ? g_list_tok[off + mr] : (off + mr);
        }
        s_arow[tid] = gr;
    }
    __syncthreads();

    const int nc = Kdim / CH_K;

#define QLOAD(c) do {                                                          \
        int _k0 = (c) * CH_K;                                                  \
        u32 _db = sb + ((c) % QNSTG) * QSTGB;                                  \
        if (tid < 256) {                                                       \
            const __half* _pa = A + (size_t)s_arow[tid] * Kdim + _k0;          \
            u32 _da = _db + tid * QROWB;                                       \
            cpa16(_da,      _pa); cpa16(_da + 16, _pa + 8);                    \
            cpa16(_da + 32, _pa + 16); cpa16(_da + 48, _pa + 24);              \
        } else {                                                               \
            int _r = (tid - 256) >> 1, _h = (tid - 256) & 1;                   \
            const __half* _p = B + (size_t)(n0 + _r) * Kdim + _k0 + _h * 16;   \
            u32 _d = _db + QOFF_B + _r * QROWB + _h * 32;                      \
            cpa16(_d, _p); cpa16(_d + 16, _p + 8);                             \
        }                                                                      \
    } while (0)

    float acc[4][4][4];
#pragma unroll
    for (int i = 0; i < 4; i++)
#pragma unroll
        for (int j = 0; j < 4; j++)
#pragma unroll
            for (int q = 0; q < 4; q++) acc[i][j][q] = 0.f;

    const int wid = tid >> 5, lane = tid & 31;
    const int wm = wid >> 2, wn = wid & 3;
    const int fr = lane & 15;
    const int fk = ((lane >> 4) & 1) * 16;

    QLOAD(0); cpa_commit();
    QLOAD(1); cpa_commit();
    QLOAD(2); cpa_commit();

    for (int c = 0; c < nc; c++) {
        if (c + 2 < nc)      asm volatile("cp.async.wait_group 2;" ::: "memory");
        else if (c + 1 < nc) asm volatile("cp.async.wait_group 1;" ::: "memory");
        else                 asm volatile("cp.async.wait_group 0;" ::: "memory");
        __syncthreads();
        if (c + 3 < nc) { QLOAD(c + 3); cpa_commit(); }

        const u32 ab = sb + (c % QNSTG) * QSTGB;
        const u32 bb = ab + QOFF_B;

#pragma unroll
        for (int kk = 0; kk < 2; kk++) {
            const int kb = kk * 32;
            u32 af[4][4], bf[2][4];
#pragma unroll
            for (int i = 0; i < 4; i++) {
                u32 ad = ab + (wm * 64 + i * 16 + fr) * QROWB + kb + fk;
                ldsm4(af[i], ad);
            }
#pragma unroll
            for (int j = 0; j < 2; j++) {
                u32 bd = bb + (wn * 32 + j * 16 + fr) * QROWB + kb + fk;
                ldsm4(bf[j], bd);
            }
#pragma unroll
            for (int i = 0; i < 4; i++)
#pragma unroll
                for (int nt = 0; nt < 4; nt++) {
                    int j = nt >> 1, t = nt & 1;
                    mma_f16(acc[i][nt], af[i], bf[j][t], bf[j][t + 2]);
                }
        }
    }

#pragma unroll
    for (int i = 0; i < 4; i++) {
#pragma unroll
        for (int h = 0; h < 2; h++) {
            int lr = wm * 64 + i * 16 + (lane >> 2) + h * 8;
            if (m0 + lr < cnt) {
                int orow = (mode == 0 ? 0 : off) + m0 + lr;
                if (epi == 0) {
                    float* crow = Cf + (size_t)orow * Nld + n0 + wn * 32;
#pragma unroll
                    for (int nt = 0; nt < 4; nt++) {
                        int col = nt * 8 + (lane & 3) * 2;
                        *(float2*)(crow + col) =
                            make_float2(acc[i][nt][h * 2], acc[i][nt][h * 2 + 1]);
                    }
                } else {
                    float w = (mode == 0) ? 1.0f : g_list_w[orow];
                    __half* hrow = Ch + (size_t)orow * (Nld / 2) + (n0 + wn * 32) / 2;
#pragma unroll
                    for (int nt = 0; nt < 4; nt++) {
                        int hcol = nt * 4 + (lane & 3);
                        float gv = acc[i][nt][h * 2];
                        float uv = acc[i][nt][h * 2 + 1];
                        float sig = 1.f / (1.f + __expf(-gv));
                        hrow[hcol] = __float2half_rn(w * (gv * sig) * uv);
                    }
                }
            }
        }
    }
#undef QLOAD
}

// ======================= launch =======================
static cudaStream_t g_s2 = nullptr;
static cudaEvent_t  g_evF = nullptr;
static cudaEvent_t  g_evJ = nullptr;

extern "C" void kernel_launch(void* const* d_in, const int* in_sizes, int n_in,
                              void* d_out, int out_size) {
    const float* x   = (const float*)d_in[0];
    const float* tcx = (const float*)d_in[1];
    const float* tpw = (const float*)d_in[2];
    const float* tpb = (const float*)d_in[3];
    const float* gw  = (const float*)d_in[4];
    const float* eg  = (const float*)d_in[5];
    const float* eu  = (const float*)d_in[6];
    const float* ed  = (const float*)d_in[7];
    const float* sg  = (const float*)d_in[8];
    const float* su  = (const float*)d_in[9];
    const float* sd  = (const float*)d_in[10];
    float* out = (float*)d_out;

    // Created once on the first (non-captured correctness) call; during graph
    // capture only kernel launches + event record/wait are issued.
    if (!g_s2) {
        cudaStreamCreateWithFlags(&g_s2, cudaStreamNonBlocking);
        cudaEventCreateWithFlags(&g_evF, cudaEventDisableTiming);
        cudaEventCreateWithFlags(&g_evJ, cudaEventDisableTiming);
        cudaFuncSetAttribute(k_gemm16, cudaFuncAttributeMaxDynamicSharedMemorySize, GEMM16_SMEM);
    }

    __half *x16, *sguT, *eguT, *sdT16, *edT16, *hs16, *he16;
    float *eout;
    cudaGetSymbolAddress((void**)&x16, g_x16);
    cudaGetSymbolAddress((void**)&sguT, g_sguT); cudaGetSymbolAddress((void**)&eguT, g_eguT);
    cudaGetSymbolAddress((void**)&sdT16, g_sdT16); cudaGetSymbolAddress((void**)&edT16, g_edT16);
    cudaGetSymbolAddress((void**)&hs16, g_hs16); cudaGetSymbolAddress((void**)&he16, g_he16);
    cudaGetSymbolAddress((void**)&eout, g_eout);

    dim3 wb(32, 8);
    int n4 = T_TOK * HDIM / 4;

    // ---- fork side stream B ----
    cudaEventRecord(g_evF, 0);
    cudaStreamWaitEvent(g_s2, g_evF, 0);

    // B: expert weight transposes + routing (independent of shared-expert chain)
    k_init<<<1, 32, 0, g_s2>>>();
    k_t16<<<dim3(IDIM/32, HDIM/32, NEXP), wb, 0, g_s2>>>(eg, eguT, HDIM, IDIM,
        (size_t)HDIM * IDIM, (size_t)2 * IDIM * HDIM, 2, 0);
    k_t16<<<dim3(IDIM/32, HDIM/32, NEXP), wb, 0, g_s2>>>(eu, eguT, HDIM, IDIM,
        (size_t)HDIM * IDIM, (size_t)2 * IDIM * HDIM, 2, 1);
    k_t16<<<dim3(HDIM/32, IDIM/32, NEXP), wb, 0, g_s2>>>(ed, edT16, IDIM, HDIM,
        (size_t)IDIM * HDIM, (size_t)IDIM * HDIM, 1, 0);
    k_w2<<<HDIM / 8, 256, 0, g_s2>>>(tpw, gw);
    k_bconst<<<1, 256, 0, g_s2>>>(tpb, gw);
    k_gate<<<T_TOK / 8, 256, 0, g_s2>>>(x, tcx, gw);
    k_offsets<<<1, 32, 0, g_s2>>>();
    k_place<<<T_TOK / 256, 256, 0, g_s2>>>();
    cudaEventRecord(g_evJ, g_s2);

    // A (main): shared-expert chain
    k_cvt16<<<n4 / 256, 256>>>(x, x16, n4);
    k_t16<<<dim3(IDIM/32, HDIM/32, 1), wb>>>(sg, sguT, HDIM, IDIM, 0, 0, 2, 0);
    k_t16<<<dim3(IDIM/32, HDIM/32, 1), wb>>>(su, sguT, HDIM, IDIM, 0, 0, 2, 1);
    k_gemm16<<<dim3(2*IDIM/128, T_TOK/256, 1), 512, GEMM16_SMEM>>>(
        x16, sguT, nullptr, hs16, HDIM, 2*IDIM, T_TOK, 0, 1);
    k_t16<<<dim3(HDIM/32, IDIM/32, 1), wb>>>(sd, sdT16, IDIM, HDIM, 0, 0, 1, 0);
    k_gemm16<<<dim3(HDIM/128, T_TOK/256, 1), 512, GEMM16_SMEM>>>(
        hs16, sdT16, out, nullptr, IDIM, HDIM, T_TOK, 0, 0);

    // ---- join B into A ----
    cudaStreamWaitEvent(0, g_evJ, 0);

    // expert path
    k_gemm16<<<dim3(2*IDIM/128, SLOTS/256, NEXP), 512, GEMM16_SMEM>>>(
        x16, eguT, nullptr, he16, HDIM, 2*IDIM, 0, 1, 1);
    k_gemm16<<<dim3(HDIM/128, SLOTS/256, NEXP), 512, GEMM16_SMEM>>>(
        he16, edT16, eout, nullptr, IDIM, HDIM, 0, 2, 0);
    k_combine<<<(T_TOK * (HDIM / 4)) / 256, 256>>>(out);
}

// round 15
// speedup vs baseline: 1.1752x; 1.0112x over previous
#include <cuda_runtime.h>
#include <cuda_bf16.h>
#include <cuda_fp16.h>
#include <stdint.h>
#include <math.h>

typedef unsigned long long u64;
typedef unsigned int u32;

#define T_TOK 4096
#define HDIM  1024
#define IDIM  2048
#define NEXP  8
#define SLOTS (2 * T_TOK)

// ======================= scratch (device globals) =======================
__device__ __align__(16) __half g_x16[(size_t)T_TOK * HDIM];
__device__ __align__(16) __half g_sguT[(size_t)(2 * IDIM) * HDIM];
__device__ __align__(16) __half g_eguT[(size_t)NEXP * (2 * IDIM) * HDIM];
__device__ __align__(16) __half g_sdT16[(size_t)HDIM * IDIM];
__device__ __align__(16) __half g_edT16[(size_t)NEXP * HDIM * IDIM];
__device__ __align__(16) __half g_hs16[(size_t)T_TOK * IDIM];
__device__ __align__(16) __half g_he16[(size_t)SLOTS * IDIM];

__device__ float g_eout[(size_t)SLOTS * HDIM];

// router folding
__device__ float g_w2[HDIM * NEXP];      // tpw @ gw
__device__ float g_bconst[NEXP];         // tpb @ gw

// routing
__device__ int   g_tok_e[T_TOK * 2];
__device__ float g_tok_w[T_TOK * 2];
__device__ int   g_tok_slot[T_TOK * 2];
__device__ int   g_counts[NEXP];
__device__ int   g_offsets[NEXP];
__device__ int   g_cursor[NEXP];
__device__ int   g_list_tok[SLOTS];
__device__ float g_list_w[SLOTS];

// ======================= PTX helpers (sm_80-era, compute_103-safe) =======================
__device__ __forceinline__ u32 smem_u32(const void* p) {
    u32 a;
    asm("{ .reg .u64 t; cvta.to.shared.u64 t, %1; cvt.u32.u64 %0, t; }" : "=r"(a) : "l"(p));
    return a;
}
__device__ __forceinline__ void cpa16(u32 dst, const void* src) {
    asm volatile("cp.async.cg.shared.global [%0], [%1], 16;"
                 :: "r"(dst), "l"(src) : "memory");
}
__device__ __forceinline__ void cpa_commit() {
    asm volatile("cp.async.commit_group;" ::: "memory");
}
__device__ __forceinline__ void ldsm4(u32* r, u32 addr) {
    asm volatile("ldmatrix.sync.aligned.m8n8.x4.shared.b16 {%0,%1,%2,%3}, [%4];"
                 : "=r"(r[0]), "=r"(r[1]), "=r"(r[2]), "=r"(r[3]) : "r"(addr));
}
__device__ __forceinline__ void mma_f16(float* c, const u32* a, u32 b0, u32 b1) {
    asm volatile("mma.sync.aligned.m16n8k16.row.col.f32.f16.f16.f32 "
                 "{%0,%1,%2,%3}, {%4,%5,%6,%7}, {%8,%9}, {%0,%1,%2,%3};"
                 : "+f"(c[0]), "+f"(c[1]), "+f"(c[2]), "+f"(c[3])
                 : "r"(a[0]), "r"(a[1]), "r"(a[2]), "r"(a[3]), "r"(b0), "r"(b1));
}

// ======================= small kernels =======================
__global__ void k_init() {
    int i = threadIdx.x;
    if (i < NEXP) { g_counts[i] = 0; g_cursor[i] = 0; }
}

__global__ void k_cvt16(const float* __restrict__ S, __half* __restrict__ H, int n4) {
    int i = blockIdx.x * blockDim.x + threadIdx.x;
    if (i >= n4) return;
    float4 v = ((const float4*)S)[i];
    union { __half b[4]; uint2 u; } uh;
    uh.b[0] = __float2half_rn(v.x); uh.b[1] = __float2half_rn(v.y);
    uh.b[2] = __float2half_rn(v.z); uh.b[3] = __float2half_rn(v.w);
    ((uint2*)H)[i] = uh.u;
}

// transpose + single fp16: W [K,N] (+z*srcZ) -> T rows (n*rowmul + phase) (+z*dstZ)
__global__ void k_t16(const float* __restrict__ W, __half* __restrict__ T,
                      int K, int N, size_t srcZ, size_t dstZ, int rowmul, int phase) {
    W += (size_t)blockIdx.z * srcZ; T += (size_t)blockIdx.z * dstZ;
    __shared__ float t[32][33];
    int k0 = blockIdx.y * 32, n0 = blockIdx.x * 32;
    int tx = threadIdx.x, ty = threadIdx.y;
#pragma unroll
    for (int q = 0; q < 4; q++)
        t[ty + 8 * q][tx] = W[(size_t)(k0 + ty + 8 * q) * N + n0 + tx];
    __syncthreads();
#pragma unroll
    for (int q = 0; q < 4; q++) {
        int n = ty + 8 * q;
        T[(size_t)((n0 + n) * rowmul + phase) * K + k0 + tx] = __float2half_rn(t[tx][n]);
    }
}

// W2[h,e] = sum_k tpw[h,k] * gw[k,e]
__global__ void k_w2(const float* __restrict__ tpw, const float* __restrict__ gw) {
    int h = (blockIdx.x * blockDim.x + threadIdx.x) >> 5;
    int lane = threadIdx.x & 31;
    if (h >= HDIM) return;
    const float* row = tpw + (size_t)h * HDIM;
    float acc[8] = {0.f,0.f,0.f,0.f,0.f,0.f,0.f,0.f};
    for (int k = lane; k < HDIM; k += 32) {
        float v = row[k];
        float4 w0 = *(const float4*)(gw + (size_t)k * 8);
        float4 w1 = *(const float4*)(gw + (size_t)k * 8 + 4);
        acc[0] += v * w0.x; acc[1] += v * w0.y; acc[2] += v * w0.z; acc[3] += v * w0.w;
        acc[4] += v * w1.x; acc[5] += v * w1.y; acc[6] += v * w1.z; acc[7] += v * w1.w;
    }
#pragma unroll
    for (int o = 16; o; o >>= 1)
#pragma unroll
        for (int e = 0; e < 8; e++) acc[e] += __shfl_down_sync(0xffffffffu, acc[e], o);
    if (lane == 0) {
#pragma unroll
        for (int e = 0; e < 8; e++) g_w2[h * 8 + e] = acc[e];
    }
}

// bconst[e] = sum_h tpb[h] * gw[h,e]
__global__ void k_bconst(const float* __restrict__ tpb, const float* __restrict__ gw) {
    __shared__ float red[256][8];
    int tid = threadIdx.x;
    float acc[8] = {0.f,0.f,0.f,0.f,0.f,0.f,0.f,0.f};
    for (int h = tid; h < HDIM; h += 256) {
        float b = tpb[h];
        float4 w0 = *(const float4*)(gw + (size_t)h * 8);
        float4 w1 = *(const float4*)(gw + (size_t)h * 8 + 4);
        acc[0] += b * w0.x; acc[1] += b * w0.y; acc[2] += b * w0.z; acc[3] += b * w0.w;
        acc[4] += b * w1.x; acc[5] += b * w1.y; acc[6] += b * w1.z; acc[7] += b * w1.w;
    }
#pragma unroll
    for (int e = 0; e < 8; e++) red[tid][e] = acc[e];
    __syncthreads();
    for (int s = 128; s; s >>= 1) {
        if (tid < s)
#pragma unroll
            for (int e = 0; e < 8; e++) red[tid][e] += red[tid + s][e];
        __syncthreads();
    }
    if (tid < 8) g_bconst[tid] = red[0][tid];
}

// fused gate: logits = x@gw + tc@W2 + bconst; softmax; top-2; histogram
__global__ void k_gate(const float* __restrict__ x, const float* __restrict__ tcx,
                       const float* __restrict__ gw) {
    int t = (blockIdx.x * blockDim.x + threadIdx.x) >> 5;
    int lane = threadIdx.x & 31;
    if (t >= T_TOK) return;
    const float* xr = x + (size_t)t * HDIM;
    const float* tr = tcx + (size_t)t * HDIM;
    float acc[8] = {0.f,0.f,0.f,0.f,0.f,0.f,0.f,0.f};
    for (int h = lane; h < HDIM; h += 32) {
        float xv = xr[h];
        float tv = tr[h];
        float4 w0 = *(const float4*)(gw + (size_t)h * 8);
        float4 w1 = *(const float4*)(gw + (size_t)h * 8 + 4);
        float4 m0 = *(const float4*)(g_w2 + (size_t)h * 8);
        float4 m1 = *(const float4*)(g_w2 + (size_t)h * 8 + 4);
        acc[0] += xv * w0.x + tv * m0.x; acc[1] += xv * w0.y + tv * m0.y;
        acc[2] += xv * w0.z + tv * m0.z; acc[3] += xv * w0.w + tv * m0.w;
        acc[4] += xv * w1.x + tv * m1.x; acc[5] += xv * w1.y + tv * m1.y;
        acc[6] += xv * w1.z + tv * m1.z; acc[7] += xv * w1.w + tv * m1.w;
    }
#pragma unroll
    for (int o = 16; o; o >>= 1)
#pragma unroll
        for (int e = 0; e < 8; e++) acc[e] += __shfl_down_sync(0xffffffffu, acc[e], o);
    if (lane == 0) {
#pragma unroll
        for (int e = 0; e < 8; e++) acc[e] += g_bconst[e];
        float mx = acc[0];
#pragma unroll
        for (int e = 1; e < 8; e++) mx = fmaxf(mx, acc[e]);
        float p[8]; float Z = 0.f;
#pragma unroll
        for (int e = 0; e < 8; e++) { p[e] = __expf(acc[e] - mx); Z += p[e]; }
        float rZ = 1.f / Z;
#pragma unroll
        for (int e = 0; e < 8; e++) p[e] *= rZ;
        int i0 = 0; float p0 = p[0];
#pragma unroll
        for (int e = 1; e < 8; e++) if (p[e] > p0) { p0 = p[e]; i0 = e; }
        int i1 = -1; float p1 = -1.f;
#pragma unroll
        for (int e = 0; e < 8; e++) if (e != i0 && p[e] > p1) { p1 = p[e]; i1 = e; }
        float s = 1.f / (p0 + p1 + 1e-5f);
        g_tok_e[2*t] = i0;     g_tok_w[2*t] = p0 * s;
        g_tok_e[2*t+1] = i1;   g_tok_w[2*t+1] = p1 * s;
        atomicAdd(&g_counts[i0], 1); atomicAdd(&g_counts[i1], 1);
    }
}

__global__ void k_offsets() {
    if (threadIdx.x == 0) {
        int s = 0;
        for (int e = 0; e < NEXP; e++) { g_offsets[e] = s; s += g_counts[e]; g_cursor[e] = 0; }
    }
}

__global__ void k_place() {
    int t = blockIdx.x * blockDim.x + threadIdx.x;
    if (t >= T_TOK) return;
#pragma unroll
    for (int k = 0; k < 2; k++) {
        int e = g_tok_e[2*t + k];
        int pos = g_offsets[e] + atomicAdd(&g_cursor[e], 1);
        g_list_tok[pos] = t;
        g_list_w[pos] = g_tok_w[2*t + k];
        g_tok_slot[2*t + k] = pos;
    }
}

__global__ void k_combine(float* __restrict__ out) {
    int gid = blockIdx.x * blockDim.x + threadIdx.x;
    int t = gid / (HDIM / 4);
    int c = (gid % (HDIM / 4)) * 4;
    if (t >= T_TOK) return;
    int s0 = g_tok_slot[2*t], s1 = g_tok_slot[2*t+1];
    float4 o = *(const float4*)(out + (size_t)t * HDIM + c);
    float4 a = *(const float4*)(g_eout + (size_t)s0 * HDIM + c);
    float4 b = *(const float4*)(g_eout + (size_t)s1 * HDIM + c);
    o.x += a.x + b.x; o.y += a.y + b.y; o.z += a.z + b.z; o.w += a.w + b.w;
    *(float4*)(out + (size_t)t * HDIM + c) = o;
}

// ======================= fp16 single-pass GEMM =======================
// C = A @ B^T. epi=0: plain fp32 store. epi=1: fused SwiGLU epilogue
// (B rows interleaved even=gate/odd=up; h=w*silu(g)*u stored fp16 at Nld/2).
// CTA 256x128, 512 threads, K-chunk 32, 4-stage ring.
// mode: 0 dense, 1 gathered tokens per expert, 2 slot rows per expert
#define CH_K    32
#define QROWB   80
#define QA_MATB (256 * QROWB)
#define QOFF_B  QA_MATB
#define QSTGB   (QA_MATB + 128 * QROWB) // 30720
#define QNSTG   4
#define GEMM16_SMEM (QNSTG * QSTGB)     // 122880

__global__ __launch_bounds__(512, 1) void k_gemm16(
    const __half* __restrict__ A, const __half* __restrict__ B,
    float* __restrict__ Cf, __half* __restrict__ Ch,
    int Kdim, int Nld, int Mdense, int mode, int epi)
{
    int cnt, off;
    if (mode == 0) { cnt = Mdense; off = 0; }
    else {
        int e = blockIdx.z;
        cnt = g_counts[e]; off = g_offsets[e];
        B += (size_t)e * Nld * Kdim;
    }
    const int m0 = blockIdx.y * 256;
    if (m0 >= cnt) return;
    const int n0 = blockIdx.x * 128;

    extern __shared__ char smem[];
    __shared__ int s_arow[256];
    const u32 sb = smem_u32(smem);
    const int tid = threadIdx.x;

    if (tid < 256) {
        int gr;
        if (mode == 0) gr = m0 + tid;
        else {
            int mr = m0 + tid; if (mr > cnt - 1) mr = cnt - 1;
            gr = (mode == 1) ? g_list_tok[off + mr] : (off + mr);
        }
        s_arow[tid] = gr;
    }
    __syncthreads();

    const int nc = Kdim / CH_K;

#define QLOAD(c) do {                                                          \
        int _k0 = (c) * CH_K;                                                  \
        u32 _db = sb + ((c) % QNSTG) * QSTGB;                                  \
        if (tid < 256) {                                                       \
            const __half* _pa = A + (size_t)s_arow[tid] * Kdim + _k0;          \
            u32 _da = _db + tid * QROWB;                                       \
            cpa16(_da,      _pa); cpa16(_da + 16, _pa + 8);                    \
            cpa16(_da + 32, _pa + 16); cpa16(_da + 48, _pa + 24);              \
        } else {                                                               \
            int _r = (tid - 256) >> 1, _h = (tid - 256) & 1;                   \
            const __half* _p = B + (size_t)(n0 + _r) * Kdim + _k0 + _h * 16;   \
            u32 _d = _db + QOFF_B + _r * QROWB + _h * 32;                      \
            cpa16(_d, _p); cpa16(_d + 16, _p + 8);                             \
        }                                                                      \
    } while (0)

    float acc[4][4][4];
#pragma unroll
    for (int i = 0; i < 4; i++)
#pragma unroll
        for (int j = 0; j < 4; j++)
#pragma unroll
            for (int q = 0; q < 4; q++) acc[i][j][q] = 0.f;

    const int wid = tid >> 5, lane = tid & 31;
    const int wm = wid >> 2, wn = wid & 3;
    const int fr = lane & 15;
    const int fk = ((lane >> 4) & 1) * 16;

    QLOAD(0); cpa_commit();
    QLOAD(1); cpa_commit();
    QLOAD(2); cpa_commit();

    for (int c = 0; c < nc; c++) {
        if (c + 2 < nc)      asm volatile("cp.async.wait_group 2;" ::: "memory");
        else if (c + 1 < nc) asm volatile("cp.async.wait_group 1;" ::: "memory");
        else                 asm volatile("cp.async.wait_group 0;" ::: "memory");
        __syncthreads();
        if (c + 3 < nc) { QLOAD(c + 3); cpa_commit(); }

        const u32 ab = sb + (c % QNSTG) * QSTGB;
        const u32 bb = ab + QOFF_B;

#pragma unroll
        for (int kk = 0; kk < 2; kk++) {
            const int kb = kk * 32;
            u32 af[4][4], bf[2][4];
#pragma unroll
            for (int i = 0; i < 4; i++) {
                u32 ad = ab + (wm * 64 + i * 16 + fr) * QROWB + kb + fk;
                ldsm4(af[i], ad);
            }
#pragma unroll
            for (int j = 0; j < 2; j++) {
                u32 bd = bb + (wn * 32 + j * 16 + fr) * QROWB + kb + fk;
                ldsm4(bf[j], bd);
            }
#pragma unroll
            for (int i = 0; i < 4; i++)
#pragma unroll
                for (int nt = 0; nt < 4; nt++) {
                    int j = nt >> 1, t = nt & 1;
                    mma_f16(acc[i][nt], af[i], bf[j][t], bf[j][t + 2]);
                }
        }
    }

#pragma unroll
    for (int i = 0; i < 4; i++) {
#pragma unroll
        for (int h = 0; h < 2; h++) {
            int lr = wm * 64 + i * 16 + (lane >> 2) + h * 8;
            if (m0 + lr < cnt) {
                int orow = (mode == 0 ? 0 : off) + m0 + lr;
                if (epi == 0) {
                    float* crow = Cf + (size_t)orow * Nld + n0 + wn * 32;
#pragma unroll
                    for (int nt = 0; nt < 4; nt++) {
                        int col = nt * 8 + (lane & 3) * 2;
                        *(float2*)(crow + col) =
                            make_float2(acc[i][nt][h * 2], acc[i][nt][h * 2 + 1]);
                    }
                } else {
                    float w = (mode == 0) ? 1.0f : g_list_w[orow];
                    __half* hrow = Ch + (size_t)orow * (Nld / 2) + (n0 + wn * 32) / 2;
#pragma unroll
                    for (int nt = 0; nt < 4; nt++) {
                        int hcol = nt * 4 + (lane & 3);
                        float gv = acc[i][nt][h * 2];
                        float uv = acc[i][nt][h * 2 + 1];
                        float sig = 1.f / (1.f + __expf(-gv));
                        hrow[hcol] = __float2half_rn(w * (gv * sig) * uv);
                    }
                }
            }
        }
    }
#undef QLOAD
}

// ======================= launch =======================
static cudaStream_t g_s2 = nullptr;
static cudaEvent_t  g_evF = nullptr;
static cudaEvent_t  g_evX = nullptr;
static cudaEvent_t  g_evJ = nullptr;

extern "C" void kernel_launch(void* const* d_in, const int* in_sizes, int n_in,
                              void* d_out, int out_size) {
    const float* x   = (const float*)d_in[0];
    const float* tcx = (const float*)d_in[1];
    const float* tpw = (const float*)d_in[2];
    const float* tpb = (const float*)d_in[3];
    const float* gw  = (const float*)d_in[4];
    const float* eg  = (const float*)d_in[5];
    const float* eu  = (const float*)d_in[6];
    const float* ed  = (const float*)d_in[7];
    const float* sg  = (const float*)d_in[8];
    const float* su  = (const float*)d_in[9];
    const float* sd  = (const float*)d_in[10];
    float* out = (float*)d_out;

    // Created once on the first (non-captured correctness) call; during graph
    // capture only kernel launches + event record/wait are issued.
    if (!g_s2) {
        cudaStreamCreateWithFlags(&g_s2, cudaStreamNonBlocking);
        cudaEventCreateWithFlags(&g_evF, cudaEventDisableTiming);
        cudaEventCreateWithFlags(&g_evX, cudaEventDisableTiming);
        cudaEventCreateWithFlags(&g_evJ, cudaEventDisableTiming);
        cudaFuncSetAttribute(k_gemm16, cudaFuncAttributeMaxDynamicSharedMemorySize, GEMM16_SMEM);
    }

    __half *x16, *sguT, *eguT, *sdT16, *edT16, *hs16, *he16;
    float *eout;
    cudaGetSymbolAddress((void**)&x16, g_x16);
    cudaGetSymbolAddress((void**)&sguT, g_sguT); cudaGetSymbolAddress((void**)&eguT, g_eguT);
    cudaGetSymbolAddress((void**)&sdT16, g_sdT16); cudaGetSymbolAddress((void**)&edT16, g_edT16);
    cudaGetSymbolAddress((void**)&hs16, g_hs16); cudaGetSymbolAddress((void**)&he16, g_he16);
    cudaGetSymbolAddress((void**)&eout, g_eout);

    dim3 wb(32, 8);
    int n4 = T_TOK * HDIM / 4;

    // ---- fork side stream B ----
    cudaEventRecord(g_evF, 0);
    cudaStreamWaitEvent(g_s2, g_evF, 0);

    // A (main): x conversion first, then signal B
    k_cvt16<<<n4 / 256, 256>>>(x, x16, n4);
    cudaEventRecord(g_evX, 0);

    // B: expert weight transposes + routing, then the FULL expert chain
    k_init<<<1, 32, 0, g_s2>>>();
    k_t16<<<dim3(IDIM/32, HDIM/32, NEXP), wb, 0, g_s2>>>(eg, eguT, HDIM, IDIM,
        (size_t)HDIM * IDIM, (size_t)2 * IDIM * HDIM, 2, 0);
    k_t16<<<dim3(IDIM/32, HDIM/32, NEXP), wb, 0, g_s2>>>(eu, eguT, HDIM, IDIM,
        (size_t)HDIM * IDIM, (size_t)2 * IDIM * HDIM, 2, 1);
    k_t16<<<dim3(HDIM/32, IDIM/32, NEXP), wb, 0, g_s2>>>(ed, edT16, IDIM, HDIM,
        (size_t)IDIM * HDIM, (size_t)IDIM * HDIM, 1, 0);
    k_w2<<<HDIM / 8, 256, 0, g_s2>>>(tpw, gw);
    k_bconst<<<1, 256, 0, g_s2>>>(tpb, gw);
    k_gate<<<T_TOK / 8, 256, 0, g_s2>>>(x, tcx, gw);
    k_offsets<<<1, 32, 0, g_s2>>>();
    k_place<<<T_TOK / 256, 256, 0, g_s2>>>();
    cudaStreamWaitEvent(g_s2, g_evX, 0);   // need x16 for expert gate+up
    k_gemm16<<<dim3(2*IDIM/128, SLOTS/256, NEXP), 512, GEMM16_SMEM, g_s2>>>(
        x16, eguT, nullptr, he16, HDIM, 2*IDIM, 0, 1, 1);
    k_gemm16<<<dim3(HDIM/128, SLOTS/256, NEXP), 512, GEMM16_SMEM, g_s2>>>(
        he16, edT16, eout, nullptr, IDIM, HDIM, 0, 2, 0);
    cudaEventRecord(g_evJ, g_s2);

    // A (main): shared-expert chain (co-runs with B's expert chain)
    k_t16<<<dim3(IDIM/32, HDIM/32, 1), wb>>>(sg, sguT, HDIM, IDIM, 0, 0, 2, 0);
    k_t16<<<dim3(IDIM/32, HDIM/32, 1), wb>>>(su, sguT, HDIM, IDIM, 0, 0, 2, 1);
    k_gemm16<<<dim3(2*IDIM/128, T_TOK/256, 1), 512, GEMM16_SMEM>>>(
        x16, sguT, nullptr, hs16, HDIM, 2*IDIM, T_TOK, 0, 1);
    k_t16<<<dim3(HDIM/32, IDIM/32, 1), wb>>>(sd, sdT16, IDIM, HDIM, 0, 0, 1, 0);
    k_gemm16<<<dim3(HDIM/128, T_TOK/256, 1), 512, GEMM16_SMEM>>>(
        hs16, sdT16, out, nullptr, IDIM, HDIM, T_TOK, 0, 0);

    // ---- join B into A ----
    cudaStreamWaitEvent(0, g_evJ, 0);
    k_combine<<<(T_TOK * (HDIM / 4)) / 256, 256>>>(out);
}

// round 16
// speedup vs baseline: 1.3015x; 1.1075x over previous
#include <cuda_runtime.h>
#include <cuda_bf16.h>
#include <cuda_fp16.h>
#include <stdint.h>
#include <math.h>

typedef unsigned long long u64;
typedef unsigned int u32;

#define T_TOK 4096
#define HDIM  1024
#define IDIM  2048
#define NEXP  8
#define SLOTS (2 * T_TOK)
#define ROWS_ALL (SLOTS + T_TOK)   // expert slots + shared rows

// ======================= scratch (device globals) =======================
__device__ __align__(16) __half g_x16[(size_t)T_TOK * HDIM];
// 9 "experts": 0..7 routed (gate/up interleaved), 8 = shared expert
__device__ __align__(16) __half g_eguT[(size_t)(NEXP + 1) * (2 * IDIM) * HDIM];
__device__ __align__(16) __half g_edT16[(size_t)(NEXP + 1) * HDIM * IDIM];
// h rows: [0,SLOTS) expert slots, [SLOTS,SLOTS+T_TOK) shared tokens
__device__ __align__(16) __half g_h16[(size_t)ROWS_ALL * IDIM];
__device__ float g_eout[(size_t)ROWS_ALL * HDIM];

// router folding
__device__ float g_w2[HDIM * NEXP];      // tpw @ gw
__device__ float g_bconst[NEXP];         // tpb @ gw

// routing
__device__ int   g_tok_e[T_TOK * 2];
__device__ float g_tok_w[T_TOK * 2];
__device__ int   g_tok_slot[T_TOK * 2];
__device__ int   g_counts[NEXP];
__device__ int   g_offsets[NEXP];
__device__ int   g_cursor[NEXP];
__device__ int   g_list_tok[SLOTS];
__device__ float g_list_w[SLOTS];

// ======================= PTX helpers (sm_80-era, compute_103-safe) =======================
__device__ __forceinline__ u32 smem_u32(const void* p) {
    u32 a;
    asm("{ .reg .u64 t; cvta.to.shared.u64 t, %1; cvt.u32.u64 %0, t; }" : "=r"(a) : "l"(p));
    return a;
}
__device__ __forceinline__ void cpa16(u32 dst, const void* src) {
    asm volatile("cp.async.cg.shared.global [%0], [%1], 16;"
                 :: "r"(dst), "l"(src) : "memory");
}
__device__ __forceinline__ void cpa_commit() {
    asm volatile("cp.async.commit_group;" ::: "memory");
}
__device__ __forceinline__ void ldsm4(u32* r, u32 addr) {
    asm volatile("ldmatrix.sync.aligned.m8n8.x4.shared.b16 {%0,%1,%2,%3}, [%4];"
                 : "=r"(r[0]), "=r"(r[1]), "=r"(r[2]), "=r"(r[3]) : "r"(addr));
}
__device__ __forceinline__ void mma_f16(float* c, const u32* a, u32 b0, u32 b1) {
    asm volatile("mma.sync.aligned.m16n8k16.row.col.f32.f16.f16.f32 "
                 "{%0,%1,%2,%3}, {%4,%5,%6,%7}, {%8,%9}, {%0,%1,%2,%3};"
                 : "+f"(c[0]), "+f"(c[1]), "+f"(c[2]), "+f"(c[3])
                 : "r"(a[0]), "r"(a[1]), "r"(a[2]), "r"(a[3]), "r"(b0), "r"(b1));
}

// ======================= small kernels =======================
__global__ void k_init() {
    int i = threadIdx.x;
    if (i < NEXP) { g_counts[i] = 0; g_cursor[i] = 0; }
}

__global__ void k_cvt16(const float* __restrict__ S, __half* __restrict__ H, int n4) {
    int i = blockIdx.x * blockDim.x + threadIdx.x;
    if (i >= n4) return;
    float4 v = ((const float4*)S)[i];
    union { __half b[4]; uint2 u; } uh;
    uh.b[0] = __float2half_rn(v.x); uh.b[1] = __float2half_rn(v.y);
    uh.b[2] = __float2half_rn(v.z); uh.b[3] = __float2half_rn(v.w);
    ((uint2*)H)[i] = uh.u;
}

// transpose + single fp16: W [K,N] (+z*srcZ) -> T rows (n*rowmul + phase) (+z*dstZ)
__global__ void k_t16(const float* __restrict__ W, __half* __restrict__ T,
                      int K, int N, size_t srcZ, size_t dstZ, int rowmul, int phase) {
    W += (size_t)blockIdx.z * srcZ; T += (size_t)blockIdx.z * dstZ;
    __shared__ float t[32][33];
    int k0 = blockIdx.y * 32, n0 = blockIdx.x * 32;
    int tx = threadIdx.x, ty = threadIdx.y;
#pragma unroll
    for (int q = 0; q < 4; q++)
        t[ty + 8 * q][tx] = W[(size_t)(k0 + ty + 8 * q) * N + n0 + tx];
    __syncthreads();
#pragma unroll
    for (int q = 0; q < 4; q++) {
        int n = ty + 8 * q;
        T[(size_t)((n0 + n) * rowmul + phase) * K + k0 + tx] = __float2half_rn(t[tx][n]);
    }
}

// W2[h,e] = sum_k tpw[h,k] * gw[k,e]
__global__ void k_w2(const float* __restrict__ tpw, const float* __restrict__ gw) {
    int h = (blockIdx.x * blockDim.x + threadIdx.x) >> 5;
    int lane = threadIdx.x & 31;
    if (h >= HDIM) return;
    const float* row = tpw + (size_t)h * HDIM;
    float acc[8] = {0.f,0.f,0.f,0.f,0.f,0.f,0.f,0.f};
    for (int k = lane; k < HDIM; k += 32) {
        float v = row[k];
        float4 w0 = *(const float4*)(gw + (size_t)k * 8);
        float4 w1 = *(const float4*)(gw + (size_t)k * 8 + 4);
        acc[0] += v * w0.x; acc[1] += v * w0.y; acc[2] += v * w0.z; acc[3] += v * w0.w;
        acc[4] += v * w1.x; acc[5] += v * w1.y; acc[6] += v * w1.z; acc[7] += v * w1.w;
    }
#pragma unroll
    for (int o = 16; o; o >>= 1)
#pragma unroll
        for (int e = 0; e < 8; e++) acc[e] += __shfl_down_sync(0xffffffffu, acc[e], o);
    if (lane == 0) {
#pragma unroll
        for (int e = 0; e < 8; e++) g_w2[h * 8 + e] = acc[e];
    }
}

// bconst[e] = sum_h tpb[h] * gw[h,e]
__global__ void k_bconst(const float* __restrict__ tpb, const float* __restrict__ gw) {
    __shared__ float red[256][8];
    int tid = threadIdx.x;
    float acc[8] = {0.f,0.f,0.f,0.f,0.f,0.f,0.f,0.f};
    for (int h = tid; h < HDIM; h += 256) {
        float b = tpb[h];
        float4 w0 = *(const float4*)(gw + (size_t)h * 8);
        float4 w1 = *(const float4*)(gw + (size_t)h * 8 + 4);
        acc[0] += b * w0.x; acc[1] += b * w0.y; acc[2] += b * w0.z; acc[3] += b * w0.w;
        acc[4] += b * w1.x; acc[5] += b * w1.y; acc[6] += b * w1.z; acc[7] += b * w1.w;
    }
#pragma unroll
    for (int e = 0; e < 8; e++) red[tid][e] = acc[e];
    __syncthreads();
    for (int s = 128; s; s >>= 1) {
        if (tid < s)
#pragma unroll
            for (int e = 0; e < 8; e++) red[tid][e] += red[tid + s][e];
        __syncthreads();
    }
    if (tid < 8) g_bconst[tid] = red[0][tid];
}

// fused gate: logits = x@gw + tc@W2 + bconst; softmax; top-2; histogram
__global__ void k_gate(const float* __restrict__ x, const float* __restrict__ tcx,
                       const float* __restrict__ gw) {
    int t = (blockIdx.x * blockDim.x + threadIdx.x) >> 5;
    int lane = threadIdx.x & 31;
    if (t >= T_TOK) return;
    const float* xr = x + (size_t)t * HDIM;
    const float* tr = tcx + (size_t)t * HDIM;
    float acc[8] = {0.f,0.f,0.f,0.f,0.f,0.f,0.f,0.f};
    for (int h = lane; h < HDIM; h += 32) {
        float xv = xr[h];
        float tv = tr[h];
        float4 w0 = *(const float4*)(gw + (size_t)h * 8);
        float4 w1 = *(const float4*)(gw + (size_t)h * 8 + 4);
        float4 m0 = *(const float4*)(g_w2 + (size_t)h * 8);
        float4 m1 = *(const float4*)(g_w2 + (size_t)h * 8 + 4);
        acc[0] += xv * w0.x + tv * m0.x; acc[1] += xv * w0.y + tv * m0.y;
        acc[2] += xv * w0.z + tv * m0.z; acc[3] += xv * w0.w + tv * m0.w;
        acc[4] += xv * w1.x + tv * m1.x; acc[5] += xv * w1.y + tv * m1.y;
        acc[6] += xv * w1.z + tv * m1.z; acc[7] += xv * w1.w + tv * m1.w;
    }
#pragma unroll
    for (int o = 16; o; o >>= 1)
#pragma unroll
        for (int e = 0; e < 8; e++) acc[e] += __shfl_down_sync(0xffffffffu, acc[e], o);
    if (lane == 0) {
#pragma unroll
        for (int e = 0; e < 8; e++) acc[e] += g_bconst[e];
        float mx = acc[0];
#pragma unroll
        for (int e = 1; e < 8; e++) mx = fmaxf(mx, acc[e]);
        float p[8]; float Z = 0.f;
#pragma unroll
        for (int e = 0; e < 8; e++) { p[e] = __expf(acc[e] - mx); Z += p[e]; }
        float rZ = 1.f / Z;
#pragma unroll
        for (int e = 0; e < 8; e++) p[e] *= rZ;
        int i0 = 0; float p0 = p[0];
#pragma unroll
        for (int e = 1; e < 8; e++) if (p[e] > p0) { p0 = p[e]; i0 = e; }
        int i1 = -1; float p1 = -1.f;
#pragma unroll
        for (int e = 0; e < 8; e++) if (e != i0 && p[e] > p1) { p1 = p[e]; i1 = e; }
        float s = 1.f / (p0 + p1 + 1e-5f);
        g_tok_e[2*t] = i0;     g_tok_w[2*t] = p0 * s;
        g_tok_e[2*t+1] = i1;   g_tok_w[2*t+1] = p1 * s;
        atomicAdd(&g_counts[i0], 1); atomicAdd(&g_counts[i1], 1);
    }
}

__global__ void k_offsets() {
    if (threadIdx.x == 0) {
        int s = 0;
        for (int e = 0; e < NEXP; e++) { g_offsets[e] = s; s += g_counts[e]; g_cursor[e] = 0; }
    }
}

__global__ void k_place() {
    int t = blockIdx.x * blockDim.x + threadIdx.x;
    if (t >= T_TOK) return;
#pragma unroll
    for (int k = 0; k < 2; k++) {
        int e = g_tok_e[2*t + k];
        int pos = g_offsets[e] + atomicAdd(&g_cursor[e], 1);
        g_list_tok[pos] = t;
        g_list_w[pos] = g_tok_w[2*t + k];
        g_tok_slot[2*t + k] = pos;
    }
}

// out[t] = eout[SLOTS+t] + eout[s0] + eout[s1]   (same add order as before)
__global__ void k_combine(float* __restrict__ out) {
    int gid = blockIdx.x * blockDim.x + threadIdx.x;
    int t = gid / (HDIM / 4);
    int c = (gid % (HDIM / 4)) * 4;
    if (t >= T_TOK) return;
    int s0 = g_tok_slot[2*t], s1 = g_tok_slot[2*t+1];
    float4 o = *(const float4*)(g_eout + (size_t)(SLOTS + t) * HDIM + c);
    float4 a = *(const float4*)(g_eout + (size_t)s0 * HDIM + c);
    float4 b = *(const float4*)(g_eout + (size_t)s1 * HDIM + c);
    o.x += a.x + b.x; o.y += a.y + b.y; o.z += a.z + b.z; o.w += a.w + b.w;
    *(float4*)(out + (size_t)t * HDIM + c) = o;
}

// ======================= fp16 single-pass GEMM (merged 9-expert) =======================
// grid z in [0, NEXP]: z<8 routed expert, z==8 shared expert (dense, off=SLOTS, w=1).
// mode 1 (gate+up): A rows gathered tokens (z<8) or identity (z=8);
//                   epilogue SwiGLU -> Ch rows off+row (Nld interleaved gate/up).
// mode 2 (down):    A rows off+row of h16; plain fp32 store -> Cf rows off+row.
#define CH_K    32
#define QROWB   80
#define QA_MATB (256 * QROWB)
#define QOFF_B  QA_MATB
#define QSTGB   (QA_MATB + 128 * QROWB) // 30720
#define QNSTG   4
#define GEMM16_SMEM (QNSTG * QSTGB)     // 122880

__global__ __launch_bounds__(512, 1) void k_gemm16(
    const __half* __restrict__ A, const __half* __restrict__ B,
    float* __restrict__ Cf, __half* __restrict__ Ch,
    int Kdim, int Nld, int mode)
{
    const int z = blockIdx.z;
    const bool se = (z == NEXP);
    const int cnt = se ? T_TOK : g_counts[z];
    const int off = se ? SLOTS : g_offsets[z];
    B += (size_t)z * Nld * Kdim;

    const int m0 = blockIdx.y * 256;
    if (m0 >= cnt) return;
    const int n0 = blockIdx.x * 128;

    extern __shared__ char smem[];
    __shared__ int s_arow[256];
    const u32 sb = smem_u32(smem);
    const int tid = threadIdx.x;

    if (tid < 256) {
        int mr = m0 + tid; if (mr > cnt - 1) mr = cnt - 1;
        int gr;
        if (mode == 1) gr = se ? mr : g_list_tok[off + mr];
        else           gr = off + mr;
        s_arow[tid] = gr;
    }
    __syncthreads();

    const int nc = Kdim / CH_K;

#define QLOAD(c) do {                                                          \
        int _k0 = (c) * CH_K;                                                  \
        u32 _db = sb + ((c) % QNSTG) * QSTGB;                                  \
        if (tid < 256) {                                                       \
            const __half* _pa = A + (size_t)s_arow[tid] * Kdim + _k0;          \
            u32 _da = _db + tid * QROWB;                                       \
            cpa16(_da,      _pa); cpa16(_da + 16, _pa + 8);                    \
            cpa16(_da + 32, _pa + 16); cpa16(_da + 48, _pa + 24);              \
        } else {                                                               \
            int _r = (tid - 256) >> 1, _h = (tid - 256) & 1;                   \
            const __half* _p = B + (size_t)(n0 + _r) * Kdim + _k0 + _h * 16;   \
            u32 _d = _db + QOFF_B + _r * QROWB + _h * 32;                      \
            cpa16(_d, _p); cpa16(_d + 16, _p + 8);                             \
        }                                                                      \
    } while (0)

    float acc[4][4][4];
#pragma unroll
    for (int i = 0; i < 4; i++)
#pragma unroll
        for (int j = 0; j < 4; j++)
#pragma unroll
            for (int q = 0; q < 4; q++) acc[i][j][q] = 0.f;

    const int wid = tid >> 5, lane = tid & 31;
    const int wm = wid >> 2, wn = wid & 3;
    const int fr = lane & 15;
    const int fk = ((lane >> 4) & 1) * 16;

    QLOAD(0); cpa_commit();
    QLOAD(1); cpa_commit();
    QLOAD(2); cpa_commit();

    for (int c = 0; c < nc; c++) {
        if (c + 2 < nc)      asm volatile("cp.async.wait_group 2;" ::: "memory");
        else if (c + 1 < nc) asm volatile("cp.async.wait_group 1;" ::: "memory");
        else                 asm volatile("cp.async.wait_group 0;" ::: "memory");
        __syncthreads();
        if (c + 3 < nc) { QLOAD(c + 3); cpa_commit(); }

        const u32 ab = sb + (c % QNSTG) * QSTGB;
        const u32 bb = ab + QOFF_B;

#pragma unroll
        for (int kk = 0; kk < 2; kk++) {
            const int kb = kk * 32;
            u32 af[4][4], bf[2][4];
#pragma unroll
            for (int i = 0; i < 4; i++) {
                u32 ad = ab + (wm * 64 + i * 16 + fr) * QROWB + kb + fk;
                ldsm4(af[i], ad);
            }
#pragma unroll
            for (int j = 0; j < 2; j++) {
                u32 bd = bb + (wn * 32 + j * 16 + fr) * QROWB + kb + fk;
                ldsm4(bf[j], bd);
            }
#pragma unroll
            for (int i = 0; i < 4; i++)
#pragma unroll
                for (int nt = 0; nt < 4; nt++) {
                    int j = nt >> 1, t = nt & 1;
                    mma_f16(acc[i][nt], af[i], bf[j][t], bf[j][t + 2]);
                }
        }
    }

#pragma unroll
    for (int i = 0; i < 4; i++) {
#pragma unroll
        for (int h = 0; h < 2; h++) {
            int lr = wm * 64 + i * 16 + (lane >> 2) + h * 8;
            if (m0 + lr < cnt) {
                int orow = off + m0 + lr;
                if (mode == 2) {
                    float* crow = Cf + (size_t)orow * Nld + n0 + wn * 32;
#pragma unroll
                    for (int nt = 0; nt < 4; nt++) {
                        int col = nt * 8 + (lane & 3) * 2;
                        *(float2*)(crow + col) =
                            make_float2(acc[i][nt][h * 2], acc[i][nt][h * 2 + 1]);
                    }
                } else {
                    float w = se ? 1.0f : g_list_w[orow];
                    __half* hrow = Ch + (size_t)orow * (Nld / 2) + (n0 + wn * 32) / 2;
#pragma unroll
                    for (int nt = 0; nt < 4; nt++) {
                        int hcol = nt * 4 + (lane & 3);
                        float gv = acc[i][nt][h * 2];
                        float uv = acc[i][nt][h * 2 + 1];
                        float sig = 1.f / (1.f + __expf(-gv));
                        hrow[hcol] = __float2half_rn(w * (gv * sig) * uv);
                    }
                }
            }
        }
    }
#undef QLOAD
}

// ======================= launch =======================
static cudaStream_t g_s2 = nullptr;
static cudaEvent_t  g_evF = nullptr;
static cudaEvent_t  g_evJ = nullptr;

extern "C" void kernel_launch(void* const* d_in, const int* in_sizes, int n_in,
                              void* d_out, int out_size) {
    const float* x   = (const float*)d_in[0];
    const float* tcx = (const float*)d_in[1];
    const float* tpw = (const float*)d_in[2];
    const float* tpb = (const float*)d_in[3];
    const float* gw  = (const float*)d_in[4];
    const float* eg  = (const float*)d_in[5];
    const float* eu  = (const float*)d_in[6];
    const float* ed  = (const float*)d_in[7];
    const float* sg  = (const float*)d_in[8];
    const float* su  = (const float*)d_in[9];
    const float* sd  = (const float*)d_in[10];
    float* out = (float*)d_out;

    if (!g_s2) {
        cudaStreamCreateWithFlags(&g_s2, cudaStreamNonBlocking);
        cudaEventCreateWithFlags(&g_evF, cudaEventDisableTiming);
        cudaEventCreateWithFlags(&g_evJ, cudaEventDisableTiming);
        cudaFuncSetAttribute(k_gemm16, cudaFuncAttributeMaxDynamicSharedMemorySize, GEMM16_SMEM);
    }

    __half *x16, *eguT, *edT16, *h16;
    float *eout;
    cudaGetSymbolAddress((void**)&x16, g_x16);
    cudaGetSymbolAddress((void**)&eguT, g_eguT);
    cudaGetSymbolAddress((void**)&edT16, g_edT16);
    cudaGetSymbolAddress((void**)&h16, g_h16);
    cudaGetSymbolAddress((void**)&eout, g_eout);

    const size_t GU_Z = (size_t)2 * IDIM * HDIM;   // per-expert gate/up block
    const size_t DN_Z = (size_t)HDIM * IDIM;       // per-expert down block

    dim3 wb(32, 8);
    int n4 = T_TOK * HDIM / 4;

    // ---- fork: B = routing chain ----
    cudaEventRecord(g_evF, 0);
    cudaStreamWaitEvent(g_s2, g_evF, 0);
    k_init<<<1, 32, 0, g_s2>>>();
    k_w2<<<HDIM / 8, 256, 0, g_s2>>>(tpw, gw);
    k_bconst<<<1, 256, 0, g_s2>>>(tpb, gw);
    k_gate<<<T_TOK / 8, 256, 0, g_s2>>>(x, tcx, gw);
    k_offsets<<<1, 32, 0, g_s2>>>();
    k_place<<<T_TOK / 256, 256, 0, g_s2>>>();
    cudaEventRecord(g_evJ, g_s2);

    // ---- A: conversions + all weight transposes ----
    k_cvt16<<<n4 / 256, 256>>>(x, x16, n4);
    // routed experts 0..7 (gate/up interleaved)
    k_t16<<<dim3(IDIM/32, HDIM/32, NEXP), wb>>>(eg, eguT, HDIM, IDIM,
        (size_t)HDIM * IDIM, GU_Z, 2, 0);
    k_t16<<<dim3(IDIM/32, HDIM/32, NEXP), wb>>>(eu, eguT, HDIM, IDIM,
        (size_t)HDIM * IDIM, GU_Z, 2, 1);
    k_t16<<<dim3(HDIM/32, IDIM/32, NEXP), wb>>>(ed, edT16, IDIM, HDIM,
        (size_t)IDIM * HDIM, DN_Z, 1, 0);
    // shared expert into slot 8
    k_t16<<<dim3(IDIM/32, HDIM/32, 1), wb>>>(sg, eguT + (size_t)NEXP * GU_Z,
        HDIM, IDIM, 0, 0, 2, 0);
    k_t16<<<dim3(IDIM/32, HDIM/32, 1), wb>>>(su, eguT + (size_t)NEXP * GU_Z,
        HDIM, IDIM, 0, 0, 2, 1);
    k_t16<<<dim3(HDIM/32, IDIM/32, 1), wb>>>(sd, edT16 + (size_t)NEXP * DN_Z,
        IDIM, HDIM, 0, 0, 1, 0);

    // ---- join routing into A ----
    cudaStreamWaitEvent(0, g_evJ, 0);

    // merged gate+up (9 experts; z=8 shared) -> h16
    k_gemm16<<<dim3(2*IDIM/128, SLOTS/256, NEXP + 1), 512, GEMM16_SMEM>>>(
        x16, eguT, nullptr, h16, HDIM, 2*IDIM, 1);
    // merged down (9 experts) -> g_eout
    k_gemm16<<<dim3(HDIM/128, SLOTS/256, NEXP + 1), 512, GEMM16_SMEM>>>(
        h16, edT16, eout, nullptr, IDIM, HDIM, 2);
    // combine
    k_combine<<<(T_TOK * (HDIM / 4)) / 256, 256>>>(out);
}